// round 12
// baseline (speedup 1.0000x reference)
#include <cuda_runtime.h>
#include <cuda_bf16.h>
#include <cstdint>

#define S_LEN  1024
#define B_SZ   8
#define E_DIM  1024
#define H_NUM  16
#define D_HEAD 64
#define NB     (B_SZ * E_DIM)           /* 8192 = s-stride in [S,B,E] */
#define NBUF   (S_LEN * B_SZ * E_DIM)   /* 8M floats */
#define M8     (1u << 23)               /* 8M elements */

typedef __nv_bfloat16 bf16;

// Scratch (no allocations allowed)
__device__ bf16  g_in[3u * M8];    // bfQin | bfKin | bfVin
__device__ bf16  g_t1[3u * M8];    // q_bf | k_bf | v_bf   (rope fused in GEMM)
__device__ bf16  g_t2[3u * M8];    // qp | kp | vp
__device__ bf16  g_att[M8];        // attention output O
__device__ bf16  g_ob[M8];         // out_proj output
__device__ float g_f[NBUF];        // final proj fp32
__device__ bf16  g_wbf[8u * 1024u * 1024u];   // bf16 weights, 8 x 1M

// ===========================================================================
// Family-portable PTX helpers (NO tcgen05 — harness compiles compute_103)
// ===========================================================================
__device__ __forceinline__ uint32_t smem_u32(const void* p) {
    uint32_t a;
    asm("{ .reg .u64 t; cvta.to.shared.u64 t, %1; cvt.u32.u64 %0, t; }"
        : "=r"(a) : "l"(p));
    return a;
}

#define LDSM_X4(d, addr)                                                        \
    asm volatile("ldmatrix.sync.aligned.m8n8.x4.shared.b16 {%0,%1,%2,%3}, [%4];"\
        : "=r"((d)[0]), "=r"((d)[1]), "=r"((d)[2]), "=r"((d)[3]) : "r"(addr))

#define LDSM_X4T(d, addr)                                                       \
    asm volatile("ldmatrix.sync.aligned.m8n8.x4.trans.shared.b16 {%0,%1,%2,%3}, [%4];"\
        : "=r"((d)[0]), "=r"((d)[1]), "=r"((d)[2]), "=r"((d)[3]) : "r"(addr))

#define MMA_BF16(ac, a, b0, b1)                                                 \
    asm volatile("mma.sync.aligned.m16n8k16.row.col.f32.bf16.bf16.f32 "         \
        "{%0,%1,%2,%3}, {%4,%5,%6,%7}, {%8,%9}, {%0,%1,%2,%3};"                 \
        : "+f"((ac)[0]), "+f"((ac)[1]), "+f"((ac)[2]), "+f"((ac)[3])            \
        : "r"((a)[0]), "r"((a)[1]), "r"((a)[2]), "r"((a)[3]),                   \
          "r"(b0), "r"(b1))

#define CP_ASYNC16(s, g)                                                        \
    asm volatile("cp.async.cg.shared.global [%0], [%1], 16;" :: "r"(s), "l"(g))
#define CP_COMMIT() asm volatile("cp.async.commit_group;" ::: "memory")
#define CP_WAIT0()  asm volatile("cp.async.wait_group 0;" ::: "memory")
#define CP_WAIT1()  asm volatile("cp.async.wait_group 1;" ::: "memory")

__device__ __forceinline__ uint32_t packbf(float x, float y) {
    __nv_bfloat162 t = __floats2bfloat162_rn(x, y);
    return *reinterpret_cast<uint32_t*>(&t);
}

// ===========================================================================
// All-bf16 mma.sync GEMM, 3-stage pipeline, CTA 128x256, warp tile 64x64.
// C[m, n] = sum_k A_row(m)[k] * Bw[n*1024 + k]; M=8192, N=1024, K=1024.
// 8 warps = 2m x 4n. Padded rows: 72 bf16 = 144 B.
// A row m at A + (m%P)*sa0 + (m/P)*sa1. grid.z batches GEMMs.
// rope_z: blocks with z < rope_z apply RoPE (pos = row%8) in epilogue.
// ===========================================================================
#define GTA   (128 * 72 * 2)       /* 18432 B  A tile */
#define GTBB  (256 * 72 * 2)       /* 36864 B  B tile */
#define STAGE (GTA + GTBB)         /* 55296 B per stage */
#define GEMM_SMEM (3 * STAGE)      /* 165888 B */

template<bool OUTBF>
__global__ __launch_bounds__(256, 1) void gemm_bf(
    const bf16* __restrict__ A0, const bf16* __restrict__ W0,
    void* __restrict__ Cv, int P, int sa0, int sa1,
    int zA, int zC, int rope_z)
{
    extern __shared__ __align__(16) char smp[];
    const uint32_t s0 = smem_u32(smp);

    const int z = blockIdx.z;
    const bf16* A  = A0 + (size_t)z * (uint32_t)zA;
    const bf16* Bw = W0 + ((size_t)z << 20);

    const int tid  = threadIdx.x;
    const int lane = tid & 31;
    const int w    = tid >> 5;
    const int wm   = w >> 2;          // 0..1
    const int wn   = w & 3;           // 0..3
    const int m_blk = blockIdx.y << 7;
    const int n_blk = blockIdx.x << 8;

    // A: 1024 chunks / 256 thr = 4 each; B: 2048 chunks / 256 thr = 8 each
    uint32_t aoff[4], ast[4];
    uint32_t boff[8], bst[8];
#pragma unroll
    for (int j = 0; j < 4; j++) {
        const int c = tid + 256 * j;
        const int row = c >> 3, sg = (c & 7) << 3;
        const int m = m_blk + row;
        aoff[j] = (uint32_t)((m % P) * sa0 + (m / P) * sa1 + sg);
        ast[j]  = s0 + (uint32_t)(row * 144 + sg * 2);
    }
#pragma unroll
    for (int j = 0; j < 8; j++) {
        const int c = tid + 256 * j;
        const int row = c >> 3, sg = (c & 7) << 3;
        boff[j] = (uint32_t)((n_blk + row) * 1024 + sg);
        bst[j]  = s0 + GTA + (uint32_t)(row * 144 + sg * 2);
    }

    const uint32_t a_lm = s0 +
        (uint32_t)((wm * 64 + (lane & 15)) * 144) + ((lane >> 4) << 4);
    const uint32_t b_lm = s0 + GTA +
        (uint32_t)((wn * 64 + (((lane >> 4) & 1) << 3) + (lane & 7)) * 144)
        + (((lane >> 3) & 1) << 4);

    float acc[4][8][4];
#pragma unroll
    for (int mt = 0; mt < 4; mt++)
#pragma unroll
        for (int nt = 0; nt < 8; nt++)
#pragma unroll
            for (int j = 0; j < 4; j++) acc[mt][nt][j] = 0.f;

    // prologue: stages 0 and 1
#pragma unroll
    for (int j = 0; j < 4; j++) CP_ASYNC16(ast[j], A + aoff[j]);
#pragma unroll
    for (int j = 0; j < 8; j++) CP_ASYNC16(bst[j], Bw + boff[j]);
    CP_COMMIT();
#pragma unroll
    for (int j = 0; j < 4; j++) CP_ASYNC16(ast[j] + STAGE, A + aoff[j] + 64);
#pragma unroll
    for (int j = 0; j < 8; j++) CP_ASYNC16(bst[j] + STAGE, Bw + boff[j] + 64);
    CP_COMMIT();
    CP_WAIT1();
    __syncthreads();

    uint32_t cb = 0, lb = 2;
    for (int i = 0; i < 16; i++) {
        if (i < 14) {
            const uint32_t ko = (uint32_t)(i + 2) << 6;
            const uint32_t lo = lb * STAGE;
#pragma unroll
            for (int j = 0; j < 4; j++) CP_ASYNC16(ast[j] + lo, A + aoff[j] + ko);
#pragma unroll
            for (int j = 0; j < 8; j++) CP_ASYNC16(bst[j] + lo, Bw + boff[j] + ko);
            CP_COMMIT();
        }

        const uint32_t co = cb * STAGE;
        const uint32_t ab = a_lm + co;
        const uint32_t bb = b_lm + co;
#pragma unroll
        for (int ks = 0; ks < 4; ks++) {
            uint32_t af[4][4];
#pragma unroll
            for (int mt = 0; mt < 4; mt++)
                LDSM_X4(af[mt], ab + ks * 32 + mt * (16 * 144));
            uint32_t bfr[4][4];
#pragma unroll
            for (int bt = 0; bt < 4; bt++)
                LDSM_X4(bfr[bt], bb + ks * 32 + bt * (16 * 144));
#pragma unroll
            for (int mt = 0; mt < 4; mt++)
#pragma unroll
                for (int nt = 0; nt < 8; nt++) {
                    const uint32_t bb0 = (nt & 1) ? bfr[nt >> 1][2] : bfr[nt >> 1][0];
                    const uint32_t bb1 = (nt & 1) ? bfr[nt >> 1][3] : bfr[nt >> 1][1];
                    MMA_BF16(acc[mt][nt], af[mt], bb0, bb1);
                }
        }

        if (i < 14)      CP_WAIT1();
        else if (i == 14) CP_WAIT0();
        __syncthreads();
        cb = (cb == 2) ? 0 : cb + 1;
        lb = (lb == 2) ? 0 : lb + 1;
    }

    const int crow0 = m_blk + wm * 64 + (lane >> 2);
    const int ccol  = n_blk + wn * 64 + ((lane & 3) << 1);

    // Fused RoPE (pos = row % 8; pair (j, j+32) = (nt, nt+4) in-thread;
    // row%8 invariant across mt since mt stride is 16)
    if (OUTBF && z < rope_z) {
        const float bpos = (float)(crow0 & 7);
        float cs[8], sn[8];
#pragma unroll
        for (int nt = 0; nt < 4; nt++)
#pragma unroll
            for (int c1 = 0; c1 < 2; c1++) {
                const int j = nt * 8 + ((lane & 3) << 1) + c1;
                const float invf = __expf(-0.28782313662425575f * (float)j);
                __sincosf(bpos * invf, &sn[nt * 2 + c1], &cs[nt * 2 + c1]);
            }
#pragma unroll
        for (int mt = 0; mt < 4; mt++)
#pragma unroll
            for (int nt = 0; nt < 4; nt++)
#pragma unroll
                for (int c = 0; c < 4; c++) {
                    const int a = nt * 2 + (c & 1);
                    const float x1 = acc[mt][nt][c], x2 = acc[mt][nt + 4][c];
                    acc[mt][nt][c]     = x1 * cs[a] - x2 * sn[a];
                    acc[mt][nt + 4][c] = x2 * cs[a] + x1 * sn[a];
                }
    }

    if (OUTBF) {
        bf16* C = (bf16*)Cv + (size_t)z * (uint32_t)zC;
#pragma unroll
        for (int mt = 0; mt < 4; mt++)
#pragma unroll
            for (int nt = 0; nt < 8; nt++) {
                bf16* cp = C + (size_t)(crow0 + mt * 16) * 1024 + ccol + nt * 8;
                *(uint32_t*)cp = packbf(acc[mt][nt][0], acc[mt][nt][1]);
                *(uint32_t*)(cp + 8 * 1024) = packbf(acc[mt][nt][2], acc[mt][nt][3]);
            }
    } else {
        float* C = (float*)Cv;
#pragma unroll
        for (int mt = 0; mt < 4; mt++)
#pragma unroll
            for (int nt = 0; nt < 8; nt++) {
                float* cp = C + (size_t)(crow0 + mt * 16) * 1024 + ccol + nt * 8;
                *(float2*)cp = make_float2(acc[mt][nt][0], acc[mt][nt][1]);
                *(float2*)(cp + 8 * 1024) = make_float2(acc[mt][nt][2], acc[mt][nt][3]);
            }
    }
}

// ===========================================================================
// Tensor-core flash attention v1 (reverted from v2 regression):
// Grid (S/64, B*H). 128 threads = 4 warps; warp = 16 q-rows x 128 keys.
// ===========================================================================
__global__ __launch_bounds__(128) void attn_mma(
    const bf16* __restrict__ qp, const bf16* __restrict__ kp,
    const bf16* __restrict__ vp, bf16* __restrict__ out)
{
    __shared__ __align__(16) bf16 Qs[64 * 72];
    __shared__ __align__(16) bf16 Ks[128 * 72];
    __shared__ __align__(16) bf16 Vs[128 * 72];

    const int tid = threadIdx.x, lane = tid & 31, w = tid >> 5;
    const int bh = blockIdx.y, b = bh >> 4, h = bh & 15;
    const int m0 = blockIdx.x << 6;
    const size_t hb = (size_t)b * E_DIM + h * D_HEAD;
    const bf16* qb = qp + hb;
    const bf16* kb = kp + hb;
    const bf16* vb = vp + hb;

    const uint32_t sQ = smem_u32(Qs), sK = smem_u32(Ks), sV = smem_u32(Vs);

#pragma unroll
    for (int j = 0; j < 4; j++) {
        const int c = tid + 128 * j;
        const int rr = c >> 3, sg = (c & 7) << 3;
        CP_ASYNC16(sQ + (uint32_t)(rr * 144 + sg * 2),
                   qb + (size_t)(m0 + rr) * NB + sg);
    }
    CP_COMMIT();

    const uint32_t aQ = sQ + (uint32_t)((w * 16 + (lane & 15)) * 144) + ((lane >> 4) << 4);
    const uint32_t bK = sK + (uint32_t)(((((lane >> 4) & 1) << 3) + (lane & 7)) * 144)
                           + (((lane >> 3) & 1) << 4);
    const uint32_t bV = sV + (uint32_t)(((lane & 7) + (((lane >> 3) & 1) << 3)) * 144)
                           + ((lane >> 4) << 4);

    float m0r = -1e30f, m1r = -1e30f, l0 = 0.f, l1 = 0.f;
    float o[8][4];
#pragma unroll
    for (int nt = 0; nt < 8; nt++)
#pragma unroll
        for (int j = 0; j < 4; j++) o[nt][j] = 0.f;

    for (int t0 = 0; t0 < S_LEN; t0 += 128) {
        __syncthreads();
#pragma unroll
        for (int j = 0; j < 8; j++) {
            const int c = tid + 128 * j;
            const int rr = c >> 3, sg = (c & 7) << 3;
            const uint32_t so = (uint32_t)(rr * 144 + sg * 2);
            const size_t go = (size_t)(t0 + rr) * NB + sg;
            CP_ASYNC16(sK + so, kb + go);
            CP_ASYNC16(sV + so, vb + go);
        }
        CP_COMMIT();
        CP_WAIT0();
        __syncthreads();

        float s[16][4];
#pragma unroll
        for (int nt = 0; nt < 16; nt++)
#pragma unroll
            for (int j = 0; j < 4; j++) s[nt][j] = 0.f;

#pragma unroll
        for (int ks = 0; ks < 4; ks++) {
            uint32_t aq[4];
            LDSM_X4(aq, aQ + ks * 32);
#pragma unroll
            for (int bt = 0; bt < 8; bt++) {
                uint32_t bk[4];
                LDSM_X4(bk, bK + bt * (16 * 144) + ks * 32);
                MMA_BF16(s[2 * bt], aq, bk[0], bk[1]);
                MMA_BF16(s[2 * bt + 1], aq, bk[2], bk[3]);
            }
        }

        float mx0 = m0r, mx1 = m1r;
#pragma unroll
        for (int nt = 0; nt < 16; nt++) {
            s[nt][0] *= 0.125f; s[nt][1] *= 0.125f;
            s[nt][2] *= 0.125f; s[nt][3] *= 0.125f;
            mx0 = fmaxf(mx0, fmaxf(s[nt][0], s[nt][1]));
            mx1 = fmaxf(mx1, fmaxf(s[nt][2], s[nt][3]));
        }
        mx0 = fmaxf(mx0, __shfl_xor_sync(0xffffffffu, mx0, 1, 4));
        mx0 = fmaxf(mx0, __shfl_xor_sync(0xffffffffu, mx0, 2, 4));
        mx1 = fmaxf(mx1, __shfl_xor_sync(0xffffffffu, mx1, 1, 4));
        mx1 = fmaxf(mx1, __shfl_xor_sync(0xffffffffu, mx1, 2, 4));
        const float f0 = __expf(m0r - mx0), f1 = __expf(m1r - mx1);
        float r0 = 0.f, r1 = 0.f;
#pragma unroll
        for (int nt = 0; nt < 16; nt++) {
            s[nt][0] = __expf(s[nt][0] - mx0);
            s[nt][1] = __expf(s[nt][1] - mx0);
            s[nt][2] = __expf(s[nt][2] - mx1);
            s[nt][3] = __expf(s[nt][3] - mx1);
            r0 += s[nt][0] + s[nt][1];
            r1 += s[nt][2] + s[nt][3];
        }
        r0 += __shfl_xor_sync(0xffffffffu, r0, 1, 4);
        r0 += __shfl_xor_sync(0xffffffffu, r0, 2, 4);
        r1 += __shfl_xor_sync(0xffffffffu, r1, 1, 4);
        r1 += __shfl_xor_sync(0xffffffffu, r1, 2, 4);
        l0 = l0 * f0 + r0; l1 = l1 * f1 + r1;
        m0r = mx0; m1r = mx1;
#pragma unroll
        for (int nt = 0; nt < 8; nt++) {
            o[nt][0] *= f0; o[nt][1] *= f0;
            o[nt][2] *= f1; o[nt][3] *= f1;
        }

#pragma unroll
        for (int kk = 0; kk < 8; kk++) {
            uint32_t pa[4];
            pa[0] = packbf(s[2 * kk][0], s[2 * kk][1]);
            pa[1] = packbf(s[2 * kk][2], s[2 * kk][3]);
            pa[2] = packbf(s[2 * kk + 1][0], s[2 * kk + 1][1]);
            pa[3] = packbf(s[2 * kk + 1][2], s[2 * kk + 1][3]);
            const uint32_t vbase = bV + kk * (16 * 144);
#pragma unroll
            for (int vt = 0; vt < 4; vt++) {
                uint32_t bv[4];
                LDSM_X4T(bv, vbase + vt * 32);
                MMA_BF16(o[2 * vt], pa, bv[0], bv[1]);
                MMA_BF16(o[2 * vt + 1], pa, bv[2], bv[3]);
            }
        }
    }

    const int row0 = m0 + w * 16 + (lane >> 2);
    const int col = (lane & 3) << 1;
    const float i0 = 1.f / l0, i1 = 1.f / l1;
    bf16* ob0 = out + (size_t)row0 * NB + hb;
    bf16* ob1 = out + (size_t)(row0 + 8) * NB + hb;
#pragma unroll
    for (int nt = 0; nt < 8; nt++) {
        *(uint32_t*)(ob0 + nt * 8 + col) = packbf(o[nt][0] * i0, o[nt][1] * i0);
        *(uint32_t*)(ob1 + nt * 8 + col) = packbf(o[nt][2] * i1, o[nt][3] * i1);
    }
}

// ===========================================================================
// Weight fp32 -> bf16 convert: 8M elements into g_wbf
// ===========================================================================
__global__ __launch_bounds__(256) void convw_kernel(
    const float* __restrict__ Wq, const float* __restrict__ Wk,
    const float* __restrict__ Wv, const float* __restrict__ inp,
    const float* __restrict__ outp, const float* __restrict__ projw,
    bf16* __restrict__ dst)
{
    const int idx = blockIdx.x * 256 + threadIdx.x;
    const size_t e = (size_t)idx << 2;
    const int seg = (int)(e >> 20);
    const size_t off = e & 0xFFFFFu;
    const float* src;
    switch (seg) {
        case 0: src = Wq; break;
        case 1: src = Wk; break;
        case 2: src = Wv; break;
        case 3: case 4: case 5: src = inp + ((size_t)(seg - 3) << 20); break;
        case 6: src = outp; break;
        default: src = projw; break;
    }
    const float4 v = *(const float4*)(src + off);
    uint2 pv;
    pv.x = packbf(v.x, v.y);
    pv.y = packbf(v.z, v.w);
    *reinterpret_cast<uint2*>(dst + e) = pv;
}

// Input activations fp32 -> bf16: [query | key | value] -> g_in (24M)
__global__ __launch_bounds__(256) void convin_kernel(
    const float* __restrict__ q, const float* __restrict__ k,
    const float* __restrict__ v, bf16* __restrict__ dst)
{
    const int idx = blockIdx.x * 256 + threadIdx.x;     // 6M threads
    const size_t e = (size_t)idx << 2;
    const int seg = (int)(e >> 23);
    const size_t off = e & (M8 - 1);
    const float* src = (seg == 0) ? q : (seg == 1) ? k : v;
    const float4 t = *(const float4*)(src + off);
    uint2 pv;
    pv.x = packbf(t.x, t.y);
    pv.y = packbf(t.z, t.w);
    *reinterpret_cast<uint2*>(dst + e) = pv;
}

// ---------------------------------------------------------------------------
// x = query + ob ; LayerNorm(last dim) * gamma + beta.
// ---------------------------------------------------------------------------
__global__ __launch_bounds__(256) void addln_kernel(
    const float* __restrict__ qin, const float* __restrict__ ob,
    const float* __restrict__ gamma, const float* __restrict__ beta,
    float* __restrict__ out)
{
    const int row = blockIdx.x;
    const int tid = threadIdx.x;
    const size_t base = (size_t)row * E_DIM;

    const float4 a = *(const float4*)(qin + base + tid*4);
    const float4 c = *(const float4*)(ob  + base + tid*4);
    const float e0 = a.x + c.x, e1 = a.y + c.y, e2 = a.z + c.z, e3 = a.w + c.w;
    float s  = e0 + e1 + e2 + e3;
    float ss = e0*e0 + e1*e1 + e2*e2 + e3*e3;
#pragma unroll
    for (int off = 16; off > 0; off >>= 1) {
        s  += __shfl_xor_sync(0xffffffffu, s,  off);
        ss += __shfl_xor_sync(0xffffffffu, ss, off);
    }
    __shared__ float sw[8], ssw[8], red[2];
    const int wid = tid >> 5, lane = tid & 31;
    if (lane == 0) { sw[wid] = s; ssw[wid] = ss; }
    __syncthreads();
    if (tid == 0) {
        float S2 = 0.f, SS = 0.f;
        for (int i = 0; i < 8; i++) { S2 += sw[i]; SS += ssw[i]; }
        red[0] = S2; red[1] = SS;
    }
    __syncthreads();
    const float mu  = red[0] * (1.0f / E_DIM);
    const float var = red[1] * (1.0f / E_DIM) - mu * mu;
    const float r   = rsqrtf(var + 1e-5f);
    const float4 g  = *(const float4*)(gamma + tid*4);
    const float4 bt = *(const float4*)(beta  + tid*4);
    float4 o;
    o.x = (e0 - mu) * r * g.x + bt.x;
    o.y = (e1 - mu) * r * g.y + bt.y;
    o.z = (e2 - mu) * r * g.z + bt.z;
    o.w = (e3 - mu) * r * g.w + bt.w;
    *(float4*)(out + base + tid*4) = o;
}

// ---------------------------------------------------------------------------
extern "C" void kernel_launch(void* const* d_in, const int* in_sizes, int n_in,
                              void* d_out, int out_size)
{
    const float* query    = (const float*)d_in[0];
    const float* key      = (const float*)d_in[1];
    const float* value    = (const float*)d_in[2];
    const float* Wq       = (const float*)d_in[3];
    const float* Wk       = (const float*)d_in[4];
    const float* Wv       = (const float*)d_in[5];
    const float* in_proj  = (const float*)d_in[6];
    const float* out_proj = (const float*)d_in[7];
    const float* proj     = (const float*)d_in[8];
    const float* gamma    = (const float*)d_in[9];
    const float* beta     = (const float*)d_in[10];
    float* out = (float*)d_out;

    bf16 *pin, *pt1, *pt2, *patt, *pob, *pwbf;
    float *pf;
    cudaGetSymbolAddress((void**)&pin,  g_in);
    cudaGetSymbolAddress((void**)&pt1,  g_t1);
    cudaGetSymbolAddress((void**)&pt2,  g_t2);
    cudaGetSymbolAddress((void**)&patt, g_att);
    cudaGetSymbolAddress((void**)&pob,  g_ob);
    cudaGetSymbolAddress((void**)&pf,   g_f);
    cudaGetSymbolAddress((void**)&pwbf, g_wbf);

    cudaFuncSetAttribute(gemm_bf<true>,
        cudaFuncAttributeMaxDynamicSharedMemorySize, GEMM_SMEM);
    cudaFuncSetAttribute(gemm_bf<false>,
        cudaFuncAttributeMaxDynamicSharedMemorySize, GEMM_SMEM);

    const size_t M1 = 1u << 20;

    // converts
    convw_kernel<<<8192, 256>>>(Wq, Wk, Wv, in_proj, out_proj, proj, pwbf);
    convin_kernel<<<24576, 256>>>(query, key, value, pin);

    // trio 1: q,k,v = swap(inputs) @ W{q,k,v}.T -> g_t1, RoPE fused for z<2
    const dim3 g3(4, 64, 3);
    gemm_bf<true><<<g3, 256, GEMM_SMEM>>>(pin, pwbf, pt1,
        B_SZ, S_LEN * E_DIM, E_DIM, (int)M8, (int)M8, 2);

    // trio 2: in_proj splits -> g_t2
    gemm_bf<true><<<g3, 256, GEMM_SMEM>>>(pt1, pwbf + 3 * M1, pt2,
        1, 0, E_DIM, (int)M8, (int)M8, 0);

    // tensor-core attention v1 -> g_att [S,B,E]
    const dim3 ga(S_LEN / 64, B_SZ * H_NUM);   // (16, 128)
    attn_mma<<<ga, 128>>>(pt2, pt2 + M8, pt2 + 2 * M8, patt);

    // out_proj -> g_ob
    const dim3 gg(4, 64, 1);
    gemm_bf<true><<<gg, 256, GEMM_SMEM>>>(patt, pwbf + 6 * M1, pob,
        1, 0, E_DIM, 0, 0, 0);

    // final proj, [S,B,E]->[B,S,E] gather (row m=b*S+s at s*NB + b*E) -> fp32
    gemm_bf<false><<<gg, 256, GEMM_SMEM>>>(pob, pwbf + 7 * M1, pf,
        S_LEN, NB, E_DIM, 0, 0, 0);

    // residual + layernorm -> out [B,S,O]
    addln_kernel<<<B_SZ * S_LEN, 256>>>(query, pf, gamma, beta, out);
}

// round 14
// speedup vs baseline: 1.1159x; 1.1159x over previous
#include <cuda_runtime.h>
#include <cuda_bf16.h>
#include <cstdint>

#define S_LEN  1024
#define B_SZ   8
#define E_DIM  1024
#define H_NUM  16
#define D_HEAD 64
#define NB     (B_SZ * E_DIM)           /* 8192 = s-stride in [S,B,E] */
#define NBUF   (S_LEN * B_SZ * E_DIM)   /* 8M floats */
#define M8     (1u << 23)               /* 8M elements */

typedef __nv_bfloat16 bf16;

// Scratch (no allocations allowed)
__device__ bf16  g_in[3u * M8];    // bfQin | bfKin | bfVin
__device__ bf16  g_t1[3u * M8];    // q_bf | k_bf | v_bf   (rope fused in GEMM)
__device__ bf16  g_t2[3u * M8];    // qp | kp | vp
__device__ bf16  g_att[M8];        // attention output O
__device__ bf16  g_ob[M8];         // out_proj output
__device__ float g_f[NBUF];        // final proj fp32
__device__ bf16  g_wbf[8u * 1024u * 1024u];   // bf16 weights, 8 x 1M

// ===========================================================================
// Family-portable PTX helpers (NO tcgen05 — harness compiles compute_103)
// ===========================================================================
__device__ __forceinline__ uint32_t smem_u32(const void* p) {
    uint32_t a;
    asm("{ .reg .u64 t; cvta.to.shared.u64 t, %1; cvt.u32.u64 %0, t; }"
        : "=r"(a) : "l"(p));
    return a;
}

#define LDSM_X4(d, addr)                                                        \
    asm volatile("ldmatrix.sync.aligned.m8n8.x4.shared.b16 {%0,%1,%2,%3}, [%4];"\
        : "=r"((d)[0]), "=r"((d)[1]), "=r"((d)[2]), "=r"((d)[3]) : "r"(addr))

#define LDSM_X4T(d, addr)                                                       \
    asm volatile("ldmatrix.sync.aligned.m8n8.x4.trans.shared.b16 {%0,%1,%2,%3}, [%4];"\
        : "=r"((d)[0]), "=r"((d)[1]), "=r"((d)[2]), "=r"((d)[3]) : "r"(addr))

#define MMA_BF16(ac, a, b0, b1)                                                 \
    asm volatile("mma.sync.aligned.m16n8k16.row.col.f32.bf16.bf16.f32 "         \
        "{%0,%1,%2,%3}, {%4,%5,%6,%7}, {%8,%9}, {%0,%1,%2,%3};"                 \
        : "+f"((ac)[0]), "+f"((ac)[1]), "+f"((ac)[2]), "+f"((ac)[3])            \
        : "r"((a)[0]), "r"((a)[1]), "r"((a)[2]), "r"((a)[3]),                   \
          "r"(b0), "r"(b1))

#define CP_ASYNC16(s, g)                                                        \
    asm volatile("cp.async.cg.shared.global [%0], [%1], 16;" :: "r"(s), "l"(g))
#define CP_COMMIT() asm volatile("cp.async.commit_group;" ::: "memory")
#define CP_WAIT0()  asm volatile("cp.async.wait_group 0;" ::: "memory")
#define CP_WAIT1()  asm volatile("cp.async.wait_group 1;" ::: "memory")

__device__ __forceinline__ uint32_t packbf(float x, float y) {
    __nv_bfloat162 t = __floats2bfloat162_rn(x, y);
    return *reinterpret_cast<uint32_t*>(&t);
}

// ===========================================================================
// All-bf16 mma.sync GEMM, 3-stage cp.async pipeline — EXACT R10 config.
// CTA 128x128, 8 warps (4m x 2n), warp tile 32x64, 2 CTAs/SM.
// C[m, n] = sum_k A_row(m)[k] * Bw[n*1024 + k]; M=8192, N=1024, K=1024.
// Padded rows: 72 bf16 = 144 B. A row m at A + (m%P)*sa0 + (m/P)*sa1.
// grid.z batches GEMMs. rope_z: z < rope_z applies RoPE (pos = row%8).
// ===========================================================================
#define GTB   (128 * 72 * 2)     /* 18432 B per tile */
#define STAGE (2 * GTB)          /* 36864 B per stage (A + B) */
#define GEMM_SMEM (3 * STAGE)    /* 110592 B */

template<bool OUTBF>
__global__ __launch_bounds__(256, 2) void gemm_bf(
    const bf16* __restrict__ A0, const bf16* __restrict__ W0,
    void* __restrict__ Cv, int P, int sa0, int sa1,
    int zA, int zC, int rope_z)
{
    extern __shared__ __align__(16) char smp[];
    const uint32_t s0 = smem_u32(smp);

    const int z = blockIdx.z;
    const bf16* A  = A0 + (size_t)z * (uint32_t)zA;
    const bf16* Bw = W0 + ((size_t)z << 20);

    const int tid  = threadIdx.x;
    const int lane = tid & 31;
    const int w    = tid >> 5;
    const int wm   = w >> 1;
    const int wn   = w & 1;
    const int m_blk = blockIdx.y << 7;
    const int n_blk = blockIdx.x << 7;

    const bf16* apt[4];
    const bf16* bpt[4];
    uint32_t ast[4], bst[4];
#pragma unroll
    for (int j = 0; j < 4; j++) {
        const int c = tid + 256 * j;
        const int row = c >> 3, sg = (c & 7) << 3;
        const int m = m_blk + row;
        apt[j] = A + (size_t)(m % P) * sa0 + (size_t)(m / P) * sa1 + sg;
        bpt[j] = Bw + (size_t)(n_blk + row) * 1024 + sg;
        ast[j] = s0 + (uint32_t)(row * 144 + sg * 2);
        bst[j] = s0 + GTB + (uint32_t)(row * 144 + sg * 2);
    }

    const uint32_t a_lm = s0 +
        (uint32_t)((wm * 32 + (lane & 15)) * 144) + ((lane >> 4) << 4);
    const uint32_t b_lm = s0 + GTB +
        (uint32_t)((wn * 64 + (((lane >> 4) & 1) << 3) + (lane & 7)) * 144)
        + (((lane >> 3) & 1) << 4);

    float acc[2][8][4];
#pragma unroll
    for (int mt = 0; mt < 2; mt++)
#pragma unroll
        for (int nt = 0; nt < 8; nt++)
#pragma unroll
            for (int j = 0; j < 4; j++) acc[mt][nt][j] = 0.f;

#pragma unroll
    for (int j = 0; j < 4; j++) {
        CP_ASYNC16(ast[j], apt[j]);
        CP_ASYNC16(bst[j], bpt[j]);
    }
    CP_COMMIT();
#pragma unroll
    for (int j = 0; j < 4; j++) {
        CP_ASYNC16(ast[j] + STAGE, apt[j] + 64);
        CP_ASYNC16(bst[j] + STAGE, bpt[j] + 64);
    }
    CP_COMMIT();
    CP_WAIT1();
    __syncthreads();

    uint32_t cb = 0, lb = 2;
    for (int i = 0; i < 16; i++) {
        if (i < 14) {
            const int ko = (i + 2) << 6;
            const uint32_t lo = lb * STAGE;
#pragma unroll
            for (int j = 0; j < 4; j++) {
                CP_ASYNC16(ast[j] + lo, apt[j] + ko);
                CP_ASYNC16(bst[j] + lo, bpt[j] + ko);
            }
            CP_COMMIT();
        }

        const uint32_t co = cb * STAGE;
        const uint32_t ab = a_lm + co;
        const uint32_t bb = b_lm + co;
#pragma unroll
        for (int ks = 0; ks < 4; ks++) {
            uint32_t af0[4], af1[4];
            LDSM_X4(af0, ab + ks * 32);
            LDSM_X4(af1, ab + ks * 32 + 16 * 144);
            uint32_t bfr[4][4];
#pragma unroll
            for (int bt = 0; bt < 4; bt++)
                LDSM_X4(bfr[bt], bb + ks * 32 + bt * 16 * 144);
#pragma unroll
            for (int nt = 0; nt < 8; nt++) {
                const uint32_t bb0 = (nt & 1) ? bfr[nt >> 1][2] : bfr[nt >> 1][0];
                const uint32_t bb1 = (nt & 1) ? bfr[nt >> 1][3] : bfr[nt >> 1][1];
                MMA_BF16(acc[0][nt], af0, bb0, bb1);
                MMA_BF16(acc[1][nt], af1, bb0, bb1);
            }
        }

        if (i < 14)      CP_WAIT1();
        else if (i == 14) CP_WAIT0();
        __syncthreads();
        cb = (cb == 2) ? 0 : cb + 1;
        lb = (lb == 2) ? 0 : lb + 1;
    }

    const int crow = m_blk + wm * 32 + (lane >> 2);
    const int ccol = n_blk + wn * 64 + ((lane & 3) << 1);

    if (OUTBF && z < rope_z) {
        const float bpos = (float)(crow & 7);
        float cs[8], sn[8];
#pragma unroll
        for (int nt = 0; nt < 4; nt++)
#pragma unroll
            for (int c1 = 0; c1 < 2; c1++) {
                const int j = nt * 8 + ((lane & 3) << 1) + c1;
                const float invf = __expf(-0.28782313662425575f * (float)j);
                __sincosf(bpos * invf, &sn[nt * 2 + c1], &cs[nt * 2 + c1]);
            }
#pragma unroll
        for (int mt = 0; mt < 2; mt++)
#pragma unroll
            for (int nt = 0; nt < 4; nt++)
#pragma unroll
                for (int c = 0; c < 4; c++) {
                    const int a = nt * 2 + (c & 1);
                    const float x1 = acc[mt][nt][c], x2 = acc[mt][nt + 4][c];
                    acc[mt][nt][c]     = x1 * cs[a] - x2 * sn[a];
                    acc[mt][nt + 4][c] = x2 * cs[a] + x1 * sn[a];
                }
    }

    if (OUTBF) {
        bf16* C = (bf16*)Cv + (size_t)z * (uint32_t)zC;
#pragma unroll
        for (int mt = 0; mt < 2; mt++)
#pragma unroll
            for (int nt = 0; nt < 8; nt++) {
                bf16* cp = C + (size_t)(crow + mt * 16) * 1024 + ccol + nt * 8;
                *(uint32_t*)cp = packbf(acc[mt][nt][0], acc[mt][nt][1]);
                *(uint32_t*)(cp + 8 * 1024) = packbf(acc[mt][nt][2], acc[mt][nt][3]);
            }
    } else {
        float* C = (float*)Cv;
#pragma unroll
        for (int mt = 0; mt < 2; mt++)
#pragma unroll
            for (int nt = 0; nt < 8; nt++) {
                float* cp = C + (size_t)(crow + mt * 16) * 1024 + ccol + nt * 8;
                *(float2*)cp = make_float2(acc[mt][nt][0], acc[mt][nt][1]);
                *(float2*)(cp + 8 * 1024) = make_float2(acc[mt][nt][2], acc[mt][nt][3]);
            }
    }
}

// ===========================================================================
// Tensor-core flash attention v3: v1 shape (64 q-rows, 128 thr, 4 warps),
// KV tile 64 rows, double-buffered K/V with wait_group 1 prefetch.
// smem: Q 9KB + 2 x (K 9KB + V 9KB) = 45KB -> 4 CTAs/SM (unchanged vs v1).
// Grid (S/64, B*H). Warp = 16 q-rows x 64 keys per tile, 16 tiles.
// ===========================================================================
#define AT64       (64 * 144)              /* 9216 B per 64x72 tile */
#define KVST       (2 * AT64)              /* K+V per stage 18432 */
#define ATTN_SMEM  (AT64 + 2 * KVST)       /* 46080 */

__global__ __launch_bounds__(128) void attn_mma(
    const bf16* __restrict__ qp, const bf16* __restrict__ kp,
    const bf16* __restrict__ vp, bf16* __restrict__ out)
{
    extern __shared__ __align__(16) char asmp[];
    const uint32_t sQ = smem_u32(asmp);
    const uint32_t sK = sQ + AT64;           // + p*KVST
    const uint32_t sV = sK + AT64;           // + p*KVST

    const int tid = threadIdx.x, lane = tid & 31, w = tid >> 5;
    const int bh = blockIdx.y, b = bh >> 4, h = bh & 15;
    const int m0 = blockIdx.x << 6;
    const size_t hb = (size_t)b * E_DIM + h * D_HEAD;
    const bf16* qb = qp + hb;
    const bf16* kb = kp + hb;
    const bf16* vb = vp + hb;

    // Q: 64 rows x 8 segs = 512 chunks / 128 thr = 4 each
#pragma unroll
    for (int j = 0; j < 4; j++) {
        const int c = tid + 128 * j;
        const int rr = c >> 3, sg = (c & 7) << 3;
        CP_ASYNC16(sQ + (uint32_t)(rr * 144 + sg * 2),
                   qb + (size_t)(m0 + rr) * NB + sg);
    }
    CP_COMMIT();

    // K/V per-tile chunk assignment: 64 rows x 8 segs = 512 / 128 = 4 each
    uint32_t kvso[4];
    size_t kvgo[4];
#pragma unroll
    for (int j = 0; j < 4; j++) {
        const int c = tid + 128 * j;
        const int rr = c >> 3, sg = (c & 7) << 3;
        kvso[j] = (uint32_t)(rr * 144 + sg * 2);
        kvgo[j] = (size_t)rr * NB + sg;
    }

    const uint32_t aQ = sQ + (uint32_t)((w * 16 + (lane & 15)) * 144) + ((lane >> 4) << 4);
    const uint32_t bKr = (uint32_t)(((((lane >> 4) & 1) << 3) + (lane & 7)) * 144)
                       + (((lane >> 3) & 1) << 4);
    const uint32_t bVr = (uint32_t)(((lane & 7) + (((lane >> 3) & 1) << 3)) * 144)
                       + ((lane >> 4) << 4);

    float m0r = -1e30f, m1r = -1e30f, l0 = 0.f, l1 = 0.f;
    float o[8][4];
#pragma unroll
    for (int nt = 0; nt < 8; nt++)
#pragma unroll
        for (int j = 0; j < 4; j++) o[nt][j] = 0.f;

    // prologue: kv tile 0 -> stage 0
#pragma unroll
    for (int j = 0; j < 4; j++) {
        CP_ASYNC16(sK + kvso[j], kb + kvgo[j]);
        CP_ASYNC16(sV + kvso[j], vb + kvgo[j]);
    }
    CP_COMMIT();

    for (int t = 0; t < 16; t++) {
        if (t < 15) {
            // prefetch t+1 into opposite stage (its previous contents were
            // consumed in iter t-1; end-of-loop barrier ordered those reads)
            const uint32_t po = (uint32_t)((t + 1) & 1) * KVST;
            const size_t go = (size_t)(t + 1) * 64 * NB;
#pragma unroll
            for (int j = 0; j < 4; j++) {
                CP_ASYNC16(sK + po + kvso[j], kb + go + kvgo[j]);
                CP_ASYNC16(sV + po + kvso[j], vb + go + kvgo[j]);
            }
            CP_COMMIT();
            CP_WAIT1();        // tile t (and Q on t=0) complete
        } else {
            CP_WAIT0();
        }
        __syncthreads();

        const uint32_t po = (uint32_t)(t & 1) * KVST;
        const uint32_t bK = sK + po + bKr;
        const uint32_t bV = sV + po + bVr;

        // S = Q K^T : 16 q-rows x 64 keys per warp
        float s[8][4];
#pragma unroll
        for (int nt = 0; nt < 8; nt++)
#pragma unroll
            for (int j = 0; j < 4; j++) s[nt][j] = 0.f;

#pragma unroll
        for (int ks = 0; ks < 4; ks++) {
            uint32_t aq[4];
            LDSM_X4(aq, aQ + ks * 32);
#pragma unroll
            for (int bt = 0; bt < 4; bt++) {
                uint32_t bk[4];
                LDSM_X4(bk, bK + bt * (16 * 144) + ks * 32);
                MMA_BF16(s[2 * bt], aq, bk[0], bk[1]);
                MMA_BF16(s[2 * bt + 1], aq, bk[2], bk[3]);
            }
        }

        // online softmax (rows r = lane>>2 and r+8)
        float mx0 = m0r, mx1 = m1r;
#pragma unroll
        for (int nt = 0; nt < 8; nt++) {
            s[nt][0] *= 0.125f; s[nt][1] *= 0.125f;
            s[nt][2] *= 0.125f; s[nt][3] *= 0.125f;
            mx0 = fmaxf(mx0, fmaxf(s[nt][0], s[nt][1]));
            mx1 = fmaxf(mx1, fmaxf(s[nt][2], s[nt][3]));
        }
        mx0 = fmaxf(mx0, __shfl_xor_sync(0xffffffffu, mx0, 1, 4));
        mx0 = fmaxf(mx0, __shfl_xor_sync(0xffffffffu, mx0, 2, 4));
        mx1 = fmaxf(mx1, __shfl_xor_sync(0xffffffffu, mx1, 1, 4));
        mx1 = fmaxf(mx1, __shfl_xor_sync(0xffffffffu, mx1, 2, 4));
        const float f0 = __expf(m0r - mx0), f1 = __expf(m1r - mx1);
        float r0 = 0.f, r1 = 0.f;
#pragma unroll
        for (int nt = 0; nt < 8; nt++) {
            s[nt][0] = __expf(s[nt][0] - mx0);
            s[nt][1] = __expf(s[nt][1] - mx0);
            s[nt][2] = __expf(s[nt][2] - mx1);
            s[nt][3] = __expf(s[nt][3] - mx1);
            r0 += s[nt][0] + s[nt][1];
            r1 += s[nt][2] + s[nt][3];
        }
        r0 += __shfl_xor_sync(0xffffffffu, r0, 1, 4);
        r0 += __shfl_xor_sync(0xffffffffu, r0, 2, 4);
        r1 += __shfl_xor_sync(0xffffffffu, r1, 1, 4);
        r1 += __shfl_xor_sync(0xffffffffu, r1, 2, 4);
        l0 = l0 * f0 + r0; l1 = l1 * f1 + r1;
        m0r = mx0; m1r = mx1;
#pragma unroll
        for (int nt = 0; nt < 8; nt++) {
            o[nt][0] *= f0; o[nt][1] *= f0;
            o[nt][2] *= f1; o[nt][3] *= f1;
        }

        // O += P V  (4 key-chunks of 16)
#pragma unroll
        for (int kk = 0; kk < 4; kk++) {
            uint32_t pa[4];
            pa[0] = packbf(s[2 * kk][0], s[2 * kk][1]);
            pa[1] = packbf(s[2 * kk][2], s[2 * kk][3]);
            pa[2] = packbf(s[2 * kk + 1][0], s[2 * kk + 1][1]);
            pa[3] = packbf(s[2 * kk + 1][2], s[2 * kk + 1][3]);
            const uint32_t vbase = bV + kk * (16 * 144);
#pragma unroll
            for (int vt = 0; vt < 4; vt++) {
                uint32_t bv[4];
                LDSM_X4T(bv, vbase + vt * 32);
                MMA_BF16(o[2 * vt], pa, bv[0], bv[1]);
                MMA_BF16(o[2 * vt + 1], pa, bv[2], bv[3]);
            }
        }
        __syncthreads();   // reads of stage (t&1) done before iter t+1 issues t+2
    }

    const int row0 = m0 + w * 16 + (lane >> 2);
    const int col = (lane & 3) << 1;
    const float i0 = 1.f / l0, i1 = 1.f / l1;
    bf16* ob0 = out + (size_t)row0 * NB + hb;
    bf16* ob1 = out + (size_t)(row0 + 8) * NB + hb;
#pragma unroll
    for (int nt = 0; nt < 8; nt++) {
        *(uint32_t*)(ob0 + nt * 8 + col) = packbf(o[nt][0] * i0, o[nt][1] * i0);
        *(uint32_t*)(ob1 + nt * 8 + col) = packbf(o[nt][2] * i1, o[nt][3] * i1);
    }
}

// ===========================================================================
// Merged convert: weights (8M elems) -> g_wbf, inputs (24M elems) -> g_in.
// 8M threads, 32768 blocks.
// ===========================================================================
__global__ __launch_bounds__(256) void conv_all(
    const float* __restrict__ Wq, const float* __restrict__ Wk,
    const float* __restrict__ Wv, const float* __restrict__ inp,
    const float* __restrict__ outp, const float* __restrict__ projw,
    const float* __restrict__ q, const float* __restrict__ k,
    const float* __restrict__ v,
    bf16* __restrict__ wdst, bf16* __restrict__ idst)
{
    const int idx = blockIdx.x * 256 + threadIdx.x;
    const float* src;
    bf16* dst;
    size_t e;
    if (idx < (1 << 21)) {                    // weights: 2M threads, 8M elems
        e = (size_t)idx << 2;
        const int seg = (int)(e >> 20);
        const size_t off = e & 0xFFFFFu;
        switch (seg) {
            case 0: src = Wq + off; break;
            case 1: src = Wk + off; break;
            case 2: src = Wv + off; break;
            case 3: case 4: case 5: src = inp + ((size_t)(seg - 3) << 20) + off; break;
            case 6: src = outp + off; break;
            default: src = projw + off; break;
        }
        dst = wdst + e;
    } else {                                  // inputs: 6M threads, 24M elems
        e = ((size_t)(idx - (1 << 21))) << 2;
        const int seg = (int)(e >> 23);
        const size_t off = e & (M8 - 1);
        src = ((seg == 0) ? q : (seg == 1) ? k : v) + off;
        dst = idst + e;
    }
    const float4 t = *(const float4*)src;
    uint2 pv;
    pv.x = packbf(t.x, t.y);
    pv.y = packbf(t.z, t.w);
    *reinterpret_cast<uint2*>(dst) = pv;
}

// ---------------------------------------------------------------------------
// x = query + ob ; LayerNorm(last dim) * gamma + beta.
// ---------------------------------------------------------------------------
__global__ __launch_bounds__(256) void addln_kernel(
    const float* __restrict__ qin, const float* __restrict__ ob,
    const float* __restrict__ gamma, const float* __restrict__ beta,
    float* __restrict__ out)
{
    const int row = blockIdx.x;
    const int tid = threadIdx.x;
    const size_t base = (size_t)row * E_DIM;

    const float4 a = *(const float4*)(qin + base + tid*4);
    const float4 c = *(const float4*)(ob  + base + tid*4);
    const float e0 = a.x + c.x, e1 = a.y + c.y, e2 = a.z + c.z, e3 = a.w + c.w;
    float s  = e0 + e1 + e2 + e3;
    float ss = e0*e0 + e1*e1 + e2*e2 + e3*e3;
#pragma unroll
    for (int off = 16; off > 0; off >>= 1) {
        s  += __shfl_xor_sync(0xffffffffu, s,  off);
        ss += __shfl_xor_sync(0xffffffffu, ss, off);
    }
    __shared__ float sw[8], ssw[8], red[2];
    const int wid = tid >> 5, lane = tid & 31;
    if (lane == 0) { sw[wid] = s; ssw[wid] = ss; }
    __syncthreads();
    if (tid == 0) {
        float S2 = 0.f, SS = 0.f;
        for (int i = 0; i < 8; i++) { S2 += sw[i]; SS += ssw[i]; }
        red[0] = S2; red[1] = SS;
    }
    __syncthreads();
    const float mu  = red[0] * (1.0f / E_DIM);
    const float var = red[1] * (1.0f / E_DIM) - mu * mu;
    const float r   = rsqrtf(var + 1e-5f);
    const float4 g  = *(const float4*)(gamma + tid*4);
    const float4 bt = *(const float4*)(beta  + tid*4);
    float4 o;
    o.x = (e0 - mu) * r * g.x + bt.x;
    o.y = (e1 - mu) * r * g.y + bt.y;
    o.z = (e2 - mu) * r * g.z + bt.z;
    o.w = (e3 - mu) * r * g.w + bt.w;
    *(float4*)(out + base + tid*4) = o;
}

// ---------------------------------------------------------------------------
extern "C" void kernel_launch(void* const* d_in, const int* in_sizes, int n_in,
                              void* d_out, int out_size)
{
    const float* query    = (const float*)d_in[0];
    const float* key      = (const float*)d_in[1];
    const float* value    = (const float*)d_in[2];
    const float* Wq       = (const float*)d_in[3];
    const float* Wk       = (const float*)d_in[4];
    const float* Wv       = (const float*)d_in[5];
    const float* in_proj  = (const float*)d_in[6];
    const float* out_proj = (const float*)d_in[7];
    const float* proj     = (const float*)d_in[8];
    const float* gamma    = (const float*)d_in[9];
    const float* beta     = (const float*)d_in[10];
    float* out = (float*)d_out;

    bf16 *pin, *pt1, *pt2, *patt, *pob, *pwbf;
    float *pf;
    cudaGetSymbolAddress((void**)&pin,  g_in);
    cudaGetSymbolAddress((void**)&pt1,  g_t1);
    cudaGetSymbolAddress((void**)&pt2,  g_t2);
    cudaGetSymbolAddress((void**)&patt, g_att);
    cudaGetSymbolAddress((void**)&pob,  g_ob);
    cudaGetSymbolAddress((void**)&pf,   g_f);
    cudaGetSymbolAddress((void**)&pwbf, g_wbf);

    cudaFuncSetAttribute(gemm_bf<true>,
        cudaFuncAttributeMaxDynamicSharedMemorySize, GEMM_SMEM);
    cudaFuncSetAttribute(gemm_bf<false>,
        cudaFuncAttributeMaxDynamicSharedMemorySize, GEMM_SMEM);
    cudaFuncSetAttribute(attn_mma,
        cudaFuncAttributeMaxDynamicSharedMemorySize, ATTN_SMEM);

    const size_t M1 = 1u << 20;

    // merged converts: weights + inputs
    conv_all<<<32768, 256>>>(Wq, Wk, Wv, in_proj, out_proj, proj,
                             query, key, value, pwbf, pin);

    // trio 1: q,k,v = swap(inputs) @ W{q,k,v}.T -> g_t1, RoPE fused for z<2
    const dim3 g3(8, 64, 3);
    gemm_bf<true><<<g3, 256, GEMM_SMEM>>>(pin, pwbf, pt1,
        B_SZ, S_LEN * E_DIM, E_DIM, (int)M8, (int)M8, 2);

    // trio 2: in_proj splits -> g_t2
    gemm_bf<true><<<g3, 256, GEMM_SMEM>>>(pt1, pwbf + 3 * M1, pt2,
        1, 0, E_DIM, (int)M8, (int)M8, 0);

    // tensor-core attention v3 -> g_att [S,B,E]
    const dim3 ga(S_LEN / 64, B_SZ * H_NUM);   // (16, 128)
    attn_mma<<<ga, 128, ATTN_SMEM>>>(pt2, pt2 + M8, pt2 + 2 * M8, patt);

    // out_proj -> g_ob
    const dim3 gg(8, 64, 1);
    gemm_bf<true><<<gg, 256, GEMM_SMEM>>>(patt, pwbf + 6 * M1, pob,
        1, 0, E_DIM, 0, 0, 0);

    // final proj, [S,B,E]->[B,S,E] gather (row m=b*S+s at s*NB + b*E) -> fp32
    gemm_bf<false><<<gg, 256, GEMM_SMEM>>>(pob, pwbf + 7 * M1, pf,
        S_LEN, NB, E_DIM, 0, 0, 0);

    // residual + layernorm -> out [B,S,O]
    addln_kernel<<<B_SZ * S_LEN, 256>>>(query, pf, gamma, beta, out);
}

// round 16
// speedup vs baseline: 1.1706x; 1.0490x over previous
#include <cuda_runtime.h>
#include <cuda_bf16.h>
#include <cstdint>

#define S_LEN  1024
#define B_SZ   8
#define E_DIM  1024
#define H_NUM  16
#define D_HEAD 64
#define NBUF   (S_LEN * B_SZ * E_DIM)   /* 8M */
#define M8     (1u << 23)               /* 8M elements */
#define M1     (1u << 20)

typedef __nv_bfloat16 bf16;

// Scratch (no allocations allowed)
__device__ bf16  g_in[3u * M8];     // bf16 inputs [B,S,E]: q | k | v
__device__ bf16  g_qkv[3u * M8];    // qp | kp | vp  [B,S,H,D]
__device__ bf16  g_att[M8];         // attention output
__device__ bf16  g_ob[M8];          // out_proj output
__device__ float g_f[NBUF];         // final proj fp32
__device__ bf16  g_ws[5u * M1];     // Wqa | Wka | Wva | out_proj | proj
__device__ bf16  g_wt[3u * M1];     // WqT | WkT | WvT
__device__ bf16  g_wa[17u * M1];    // WA_q(8) | WA_k(8) | Wva copy
__device__ bf16  g_wc[17u * M1];    // Wqc(8) | Wkc(8) | Wvc

// ===========================================================================
// Family-portable PTX helpers (NO tcgen05 — harness compiles compute_103)
// ===========================================================================
__device__ __forceinline__ uint32_t smem_u32(const void* p) {
    uint32_t a;
    asm("{ .reg .u64 t; cvta.to.shared.u64 t, %1; cvt.u32.u64 %0, t; }"
        : "=r"(a) : "l"(p));
    return a;
}

__device__ __forceinline__ float ex2f(float x) {
    float r;
    asm("ex2.approx.ftz.f32 %0, %1;" : "=f"(r) : "f"(x));
    return r;
}

#define LDSM_X4(d, addr)                                                        \
    asm volatile("ldmatrix.sync.aligned.m8n8.x4.shared.b16 {%0,%1,%2,%3}, [%4];"\
        : "=r"((d)[0]), "=r"((d)[1]), "=r"((d)[2]), "=r"((d)[3]) : "r"(addr))

#define LDSM_X4T(d, addr)                                                       \
    asm volatile("ldmatrix.sync.aligned.m8n8.x4.trans.shared.b16 {%0,%1,%2,%3}, [%4];"\
        : "=r"((d)[0]), "=r"((d)[1]), "=r"((d)[2]), "=r"((d)[3]) : "r"(addr))

#define MMA_BF16(ac, a, b0, b1)                                                 \
    asm volatile("mma.sync.aligned.m16n8k16.row.col.f32.bf16.bf16.f32 "         \
        "{%0,%1,%2,%3}, {%4,%5,%6,%7}, {%8,%9}, {%0,%1,%2,%3};"                 \
        : "+f"((ac)[0]), "+f"((ac)[1]), "+f"((ac)[2]), "+f"((ac)[3])            \
        : "r"((a)[0]), "r"((a)[1]), "r"((a)[2]), "r"((a)[3]),                   \
          "r"(b0), "r"(b1))

#define CP_ASYNC16(s, g)                                                        \
    asm volatile("cp.async.cg.shared.global [%0], [%1], 16;" :: "r"(s), "l"(g))
#define CP_COMMIT() asm volatile("cp.async.commit_group;" ::: "memory")
#define CP_WAIT0()  asm volatile("cp.async.wait_group 0;" ::: "memory")
#define CP_WAIT1()  asm volatile("cp.async.wait_group 1;" ::: "memory")

__device__ __forceinline__ uint32_t packbf(float x, float y) {
    __nv_bfloat162 t = __floats2bfloat162_rn(x, y);
    return *reinterpret_cast<uint32_t*>(&t);
}
__device__ __forceinline__ void unpack2(uint32_t u, float& a, float& b) {
    __nv_bfloat162 t = *reinterpret_cast<__nv_bfloat162*>(&u);
    a = __bfloat162float(t.x); b = __bfloat162float(t.y);
}

#define QSCALE 0.18033688011112043f   /* 0.125 * log2(e) */

// ===========================================================================
// All-bf16 mma.sync GEMM, 3-stage pipeline — R10 shape (CTA 128x128, 2/SM).
// C[m, n] = sum_k A_row(m)[k] * W[n*1024 + k].
// A = A0 + z*zA, row m at m*1024 (all inputs contiguous now).
// wsel: 0 -> W = W0 (single matrix)
//       1 -> W = W0 + (z>>3)*1M, epilogue scale QSCALE when z<8 (weight GEMM)
//       2 -> W = W0 + (z<2 ? (z*8 + (m_blk>>10))*1M : 16*1M)   (activation trio)
// ===========================================================================
#define GTB   (128 * 72 * 2)     /* 18432 B per tile */
#define STAGE (2 * GTB)          /* 36864 B per stage (A + B) */
#define GEMM_SMEM (3 * STAGE)    /* 110592 B */

template<bool OUTBF>
__global__ __launch_bounds__(256, 2) void gemm_bf(
    const bf16* __restrict__ A0, const bf16* __restrict__ W0,
    void* __restrict__ Cv, int zA, int zC, int wsel)
{
    extern __shared__ __align__(16) char smp[];
    const uint32_t s0 = smem_u32(smp);

    const int z = blockIdx.z;
    const int m_blk = blockIdx.y << 7;
    const int n_blk = blockIdx.x << 7;

    const bf16* A = A0 + (size_t)z * (uint32_t)zA;
    const bf16* Bw;
    if (wsel == 1)      Bw = W0 + ((size_t)(z >> 3) << 20);
    else if (wsel == 2) Bw = W0 + ((size_t)((z < 2) ? (z * 8 + (m_blk >> 10)) : 16) << 20);
    else                Bw = W0;

    const int tid  = threadIdx.x;
    const int lane = tid & 31;
    const int w    = tid >> 5;
    const int wm   = w >> 1;
    const int wn   = w & 1;

    const bf16* apt[4];
    const bf16* bpt[4];
    uint32_t ast[4], bst[4];
#pragma unroll
    for (int j = 0; j < 4; j++) {
        const int c = tid + 256 * j;
        const int row = c >> 3, sg = (c & 7) << 3;
        apt[j] = A + (size_t)(m_blk + row) * 1024 + sg;
        bpt[j] = Bw + (size_t)(n_blk + row) * 1024 + sg;
        ast[j] = s0 + (uint32_t)(row * 144 + sg * 2);
        bst[j] = s0 + GTB + (uint32_t)(row * 144 + sg * 2);
    }

    const uint32_t a_lm = s0 +
        (uint32_t)((wm * 32 + (lane & 15)) * 144) + ((lane >> 4) << 4);
    const uint32_t b_lm = s0 + GTB +
        (uint32_t)((wn * 64 + (((lane >> 4) & 1) << 3) + (lane & 7)) * 144)
        + (((lane >> 3) & 1) << 4);

    float acc[2][8][4];
#pragma unroll
    for (int mt = 0; mt < 2; mt++)
#pragma unroll
        for (int nt = 0; nt < 8; nt++)
#pragma unroll
            for (int j = 0; j < 4; j++) acc[mt][nt][j] = 0.f;

#pragma unroll
    for (int j = 0; j < 4; j++) {
        CP_ASYNC16(ast[j], apt[j]);
        CP_ASYNC16(bst[j], bpt[j]);
    }
    CP_COMMIT();
#pragma unroll
    for (int j = 0; j < 4; j++) {
        CP_ASYNC16(ast[j] + STAGE, apt[j] + 64);
        CP_ASYNC16(bst[j] + STAGE, bpt[j] + 64);
    }
    CP_COMMIT();
    CP_WAIT1();
    __syncthreads();

    uint32_t cb = 0, lb = 2;
    for (int i = 0; i < 16; i++) {
        if (i < 14) {
            const int ko = (i + 2) << 6;
            const uint32_t lo = lb * STAGE;
#pragma unroll
            for (int j = 0; j < 4; j++) {
                CP_ASYNC16(ast[j] + lo, apt[j] + ko);
                CP_ASYNC16(bst[j] + lo, bpt[j] + ko);
            }
            CP_COMMIT();
        }

        const uint32_t co = cb * STAGE;
        const uint32_t ab = a_lm + co;
        const uint32_t bb = b_lm + co;
#pragma unroll
        for (int ks = 0; ks < 4; ks++) {
            uint32_t af0[4], af1[4];
            LDSM_X4(af0, ab + ks * 32);
            LDSM_X4(af1, ab + ks * 32 + 16 * 144);
            uint32_t bfr[4][4];
#pragma unroll
            for (int bt = 0; bt < 4; bt++)
                LDSM_X4(bfr[bt], bb + ks * 32 + bt * 16 * 144);
#pragma unroll
            for (int nt = 0; nt < 8; nt++) {
                const uint32_t bb0 = (nt & 1) ? bfr[nt >> 1][2] : bfr[nt >> 1][0];
                const uint32_t bb1 = (nt & 1) ? bfr[nt >> 1][3] : bfr[nt >> 1][1];
                MMA_BF16(acc[0][nt], af0, bb0, bb1);
                MMA_BF16(acc[1][nt], af1, bb0, bb1);
            }
        }

        if (i < 14)      CP_WAIT1();
        else if (i == 14) CP_WAIT0();
        __syncthreads();
        cb = (cb == 2) ? 0 : cb + 1;
        lb = (lb == 2) ? 0 : lb + 1;
    }

    // q-side score scale folded into combined weights
    if (wsel == 1 && z < 8) {
#pragma unroll
        for (int mt = 0; mt < 2; mt++)
#pragma unroll
            for (int nt = 0; nt < 8; nt++)
#pragma unroll
                for (int j = 0; j < 4; j++) acc[mt][nt][j] *= QSCALE;
    }

    const int crow = m_blk + wm * 32 + (lane >> 2);
    const int ccol = n_blk + wn * 64 + ((lane & 3) << 1);
    if (OUTBF) {
        bf16* C = (bf16*)Cv + (size_t)z * (uint32_t)zC;
#pragma unroll
        for (int mt = 0; mt < 2; mt++)
#pragma unroll
            for (int nt = 0; nt < 8; nt++) {
                bf16* cp = C + (size_t)(crow + mt * 16) * 1024 + ccol + nt * 8;
                *(uint32_t*)cp = packbf(acc[mt][nt][0], acc[mt][nt][1]);
                *(uint32_t*)(cp + 8 * 1024) = packbf(acc[mt][nt][2], acc[mt][nt][3]);
            }
    } else {
        float* C = (float*)Cv;
#pragma unroll
        for (int mt = 0; mt < 2; mt++)
#pragma unroll
            for (int nt = 0; nt < 8; nt++) {
                float* cp = C + (size_t)(crow + mt * 16) * 1024 + ccol + nt * 8;
                *(float2*)cp = make_float2(acc[mt][nt][0], acc[mt][nt][1]);
                *(float2*)(cp + 8 * 1024) = make_float2(acc[mt][nt][2], acc[mt][nt][3]);
            }
    }
}

// ===========================================================================
// Tensor-core flash attention, [B,S,H,D] layouts, exp2 softmax (scale folded
// into qp). 64 q-rows/CTA, 128 thr, double-buffered 64-row K/V tiles.
// ===========================================================================
#define AT64       (64 * 144)
#define KVST       (2 * AT64)
#define ATTN_SMEM  (AT64 + 2 * KVST)       /* 46080 */

__global__ __launch_bounds__(128) void attn_mma(
    const bf16* __restrict__ qp, const bf16* __restrict__ kp,
    const bf16* __restrict__ vp, bf16* __restrict__ out)
{
    extern __shared__ __align__(16) char asmp[];
    const uint32_t sQ = smem_u32(asmp);
    const uint32_t sK = sQ + AT64;
    const uint32_t sV = sK + AT64;

    const int tid = threadIdx.x, lane = tid & 31, w = tid >> 5;
    const int bh = blockIdx.y, b = bh >> 4, h = bh & 15;
    const int m0 = blockIdx.x << 6;
    const size_t hb = (size_t)b * S_LEN * E_DIM + h * D_HEAD;
    const bf16* qb = qp + hb;
    const bf16* kb = kp + hb;
    const bf16* vb = vp + hb;

#pragma unroll
    for (int j = 0; j < 4; j++) {
        const int c = tid + 128 * j;
        const int rr = c >> 3, sg = (c & 7) << 3;
        CP_ASYNC16(sQ + (uint32_t)(rr * 144 + sg * 2),
                   qb + (size_t)(m0 + rr) * E_DIM + sg);
    }
    CP_COMMIT();

    uint32_t kvso[4];
    size_t kvgo[4];
#pragma unroll
    for (int j = 0; j < 4; j++) {
        const int c = tid + 128 * j;
        const int rr = c >> 3, sg = (c & 7) << 3;
        kvso[j] = (uint32_t)(rr * 144 + sg * 2);
        kvgo[j] = (size_t)rr * E_DIM + sg;
    }

    const uint32_t aQ = sQ + (uint32_t)((w * 16 + (lane & 15)) * 144) + ((lane >> 4) << 4);
    const uint32_t bKr = (uint32_t)(((((lane >> 4) & 1) << 3) + (lane & 7)) * 144)
                       + (((lane >> 3) & 1) << 4);
    const uint32_t bVr = (uint32_t)(((lane & 7) + (((lane >> 3) & 1) << 3)) * 144)
                       + ((lane >> 4) << 4);

    float m0r = -1e30f, m1r = -1e30f, l0 = 0.f, l1 = 0.f;
    float o[8][4];
#pragma unroll
    for (int nt = 0; nt < 8; nt++)
#pragma unroll
        for (int j = 0; j < 4; j++) o[nt][j] = 0.f;

#pragma unroll
    for (int j = 0; j < 4; j++) {
        CP_ASYNC16(sK + kvso[j], kb + kvgo[j]);
        CP_ASYNC16(sV + kvso[j], vb + kvgo[j]);
    }
    CP_COMMIT();

    for (int t = 0; t < 16; t++) {
        if (t < 15) {
            const uint32_t po = (uint32_t)((t + 1) & 1) * KVST;
            const size_t go = (size_t)(t + 1) * 64 * E_DIM;
#pragma unroll
            for (int j = 0; j < 4; j++) {
                CP_ASYNC16(sK + po + kvso[j], kb + go + kvgo[j]);
                CP_ASYNC16(sV + po + kvso[j], vb + go + kvgo[j]);
            }
            CP_COMMIT();
            CP_WAIT1();
        } else {
            CP_WAIT0();
        }
        __syncthreads();

        const uint32_t po = (uint32_t)(t & 1) * KVST;
        const uint32_t bK = sK + po + bKr;
        const uint32_t bV = sV + po + bVr;

        float s[8][4];
#pragma unroll
        for (int nt = 0; nt < 8; nt++)
#pragma unroll
            for (int j = 0; j < 4; j++) s[nt][j] = 0.f;

#pragma unroll
        for (int ks = 0; ks < 4; ks++) {
            uint32_t aq[4];
            LDSM_X4(aq, aQ + ks * 32);
#pragma unroll
            for (int bt = 0; bt < 4; bt++) {
                uint32_t bk[4];
                LDSM_X4(bk, bK + bt * (16 * 144) + ks * 32);
                MMA_BF16(s[2 * bt], aq, bk[0], bk[1]);
                MMA_BF16(s[2 * bt + 1], aq, bk[2], bk[3]);
            }
        }

        // online softmax in log2 domain (scale pre-folded into qp)
        float mx0 = m0r, mx1 = m1r;
#pragma unroll
        for (int nt = 0; nt < 8; nt++) {
            mx0 = fmaxf(mx0, fmaxf(s[nt][0], s[nt][1]));
            mx1 = fmaxf(mx1, fmaxf(s[nt][2], s[nt][3]));
        }
        mx0 = fmaxf(mx0, __shfl_xor_sync(0xffffffffu, mx0, 1, 4));
        mx0 = fmaxf(mx0, __shfl_xor_sync(0xffffffffu, mx0, 2, 4));
        mx1 = fmaxf(mx1, __shfl_xor_sync(0xffffffffu, mx1, 1, 4));
        mx1 = fmaxf(mx1, __shfl_xor_sync(0xffffffffu, mx1, 2, 4));
        const float f0 = ex2f(m0r - mx0), f1 = ex2f(m1r - mx1);
        float r0 = 0.f, r1 = 0.f;
#pragma unroll
        for (int nt = 0; nt < 8; nt++) {
            s[nt][0] = ex2f(s[nt][0] - mx0);
            s[nt][1] = ex2f(s[nt][1] - mx0);
            s[nt][2] = ex2f(s[nt][2] - mx1);
            s[nt][3] = ex2f(s[nt][3] - mx1);
            r0 += s[nt][0] + s[nt][1];
            r1 += s[nt][2] + s[nt][3];
        }
        r0 += __shfl_xor_sync(0xffffffffu, r0, 1, 4);
        r0 += __shfl_xor_sync(0xffffffffu, r0, 2, 4);
        r1 += __shfl_xor_sync(0xffffffffu, r1, 1, 4);
        r1 += __shfl_xor_sync(0xffffffffu, r1, 2, 4);
        l0 = l0 * f0 + r0; l1 = l1 * f1 + r1;
        m0r = mx0; m1r = mx1;
#pragma unroll
        for (int nt = 0; nt < 8; nt++) {
            o[nt][0] *= f0; o[nt][1] *= f0;
            o[nt][2] *= f1; o[nt][3] *= f1;
        }

#pragma unroll
        for (int kk = 0; kk < 4; kk++) {
            uint32_t pa[4];
            pa[0] = packbf(s[2 * kk][0], s[2 * kk][1]);
            pa[1] = packbf(s[2 * kk][2], s[2 * kk][3]);
            pa[2] = packbf(s[2 * kk + 1][0], s[2 * kk + 1][1]);
            pa[3] = packbf(s[2 * kk + 1][2], s[2 * kk + 1][3]);
            const uint32_t vbase = bV + kk * (16 * 144);
#pragma unroll
            for (int vt = 0; vt < 4; vt++) {
                uint32_t bv[4];
                LDSM_X4T(bv, vbase + vt * 32);
                MMA_BF16(o[2 * vt], pa, bv[0], bv[1]);
                MMA_BF16(o[2 * vt + 1], pa, bv[2], bv[3]);
            }
        }
        __syncthreads();
    }

    const int row0 = m0 + w * 16 + (lane >> 2);
    const int col = (lane & 3) << 1;
    const float i0 = 1.f / l0, i1 = 1.f / l1;
    bf16* ob0 = out + hb + (size_t)row0 * E_DIM;
    bf16* ob1 = ob0 + 8 * E_DIM;
#pragma unroll
    for (int nt = 0; nt < 8; nt++) {
        *(uint32_t*)(ob0 + nt * 8 + col) = packbf(o[nt][0] * i0, o[nt][1] * i0);
        *(uint32_t*)(ob1 + nt * 8 + col) = packbf(o[nt][2] * i1, o[nt][3] * i1);
    }
}

// ===========================================================================
// conv_all: in_proj(3M)+out_proj(1M)+proj(1M) -> g_ws; inputs(24M) -> g_in
// ===========================================================================
__global__ __launch_bounds__(256) void conv_all(
    const float* __restrict__ inp, const float* __restrict__ outp,
    const float* __restrict__ projw,
    const float* __restrict__ q, const float* __restrict__ k,
    const float* __restrict__ v,
    bf16* __restrict__ wdst, bf16* __restrict__ idst)
{
    const int idx = blockIdx.x * 256 + threadIdx.x;
    const float* src;
    bf16* dst;
    if (idx < (5 << 18)) {                    // weights: 1.25M threads / 5M elems
        const size_t e = (size_t)idx << 2;
        const int seg = (int)(e >> 20);
        const size_t off = e & 0xFFFFFu;
        if (seg < 3)      src = inp + ((size_t)seg << 20) + off;
        else if (seg == 3) src = outp + off;
        else               src = projw + off;
        dst = wdst + e;
    } else {                                  // inputs: 6M threads / 24M elems
        const size_t e = (size_t)(idx - (5 << 18)) << 2;
        const int seg = (int)(e >> 23);
        const size_t off = e & (M8 - 1);
        src = ((seg == 0) ? q : (seg == 1) ? k : v) + off;
        dst = idst + e;
    }
    const float4 t = *(const float4*)src;
    uint2 pv;
    pv.x = packbf(t.x, t.y);
    pv.y = packbf(t.z, t.w);
    *reinterpret_cast<uint2*>(dst) = pv;
}

// ===========================================================================
// Tiled transpose-convert: Wq/Wk/Wv fp32 [1024,1024] -> bf16 transposed g_wt
// grid (32, 32, 3), block (32, 8)
// ===========================================================================
__global__ __launch_bounds__(256) void transconv(
    const float* __restrict__ Wq, const float* __restrict__ Wk,
    const float* __restrict__ Wv, bf16* __restrict__ wt)
{
    __shared__ float tile[32][33];
    const int z = blockIdx.z;
    const float* src = (z == 0) ? Wq : (z == 1) ? Wk : Wv;
    bf16* dst = wt + ((size_t)z << 20);
    const int x0 = blockIdx.x << 5, e0 = blockIdx.y << 5;
    const int tx = threadIdx.x, ty = threadIdx.y;
#pragma unroll
    for (int i = ty; i < 32; i += 8)
        tile[i][tx] = src[(size_t)(e0 + i) * 1024 + x0 + tx];
    __syncthreads();
#pragma unroll
    for (int i = ty; i < 32; i += 8)
        dst[(size_t)(x0 + i) * 1024 + e0 + tx] = __float2bfloat16(tile[tx][i]);
}

// ===========================================================================
// ropew: build WA = [Wqa*R_b (b=0..7) | Wka*R_b (b=0..7) | Wva copy]  (17M)
// (W*R_b)[n,e] : e-half pairing (j, j+32) within each 64-dim head.
// ===========================================================================
__global__ __launch_bounds__(256) void ropew_kernel(
    const bf16* __restrict__ ws, bf16* __restrict__ wa)
{
    const int idx = blockIdx.x * 256 + threadIdx.x;   // 17M/4 threads
    const size_t gi = (size_t)idx << 2;
    const int z = (int)(gi >> 20);
    const uint32_t r = (uint32_t)(gi & 0xFFFFFu);
    if (z >= 16) {
        *(uint2*)(wa + gi) = *(const uint2*)(ws + (2u << 20) + r);
        return;
    }
    const bf16* W = ws + ((z >= 8) ? (1u << 20) : 0u);
    const float bpos = (float)(z & 7);
    const uint32_t n = r >> 10, e = r & 1023u;
    const int jj = (int)(e & 63);
    const bool lo = (jj < 32);
    const size_t base = (size_t)n * 1024 + e;
    uint2 tp = *(const uint2*)(W + base);
    uint2 tq = *(const uint2*)(W + base + (lo ? 32 : -32));
    float p[4], q4[4];
    unpack2(tp.x, p[0], p[1]); unpack2(tp.y, p[2], p[3]);
    unpack2(tq.x, q4[0], q4[1]); unpack2(tq.y, q4[2], q4[3]);
    float v[4];
#pragma unroll
    for (int c = 0; c < 4; c++) {
        const int j2 = lo ? (jj + c) : (jj + c - 32);
        const float inv = __expf(-0.28782313662425575f * (float)j2);
        float sn, cs;
        __sincosf(bpos * inv, &sn, &cs);
        v[c] = lo ? (p[c] * cs + q4[c] * sn) : (p[c] * cs - q4[c] * sn);
    }
    uint2 pv;
    pv.x = packbf(v[0], v[1]);
    pv.y = packbf(v[2], v[3]);
    *(uint2*)(wa + gi) = pv;
}

// ---------------------------------------------------------------------------
// x = query + ob ; LayerNorm(last dim) * gamma + beta.
// ---------------------------------------------------------------------------
__global__ __launch_bounds__(256) void addln_kernel(
    const float* __restrict__ qin, const float* __restrict__ ob,
    const float* __restrict__ gamma, const float* __restrict__ beta,
    float* __restrict__ out)
{
    const int row = blockIdx.x;
    const int tid = threadIdx.x;
    const size_t base = (size_t)row * E_DIM;

    const float4 a = *(const float4*)(qin + base + tid*4);
    const float4 c = *(const float4*)(ob  + base + tid*4);
    const float e0 = a.x + c.x, e1 = a.y + c.y, e2 = a.z + c.z, e3 = a.w + c.w;
    float s  = e0 + e1 + e2 + e3;
    float ss = e0*e0 + e1*e1 + e2*e2 + e3*e3;
#pragma unroll
    for (int off = 16; off > 0; off >>= 1) {
        s  += __shfl_xor_sync(0xffffffffu, s,  off);
        ss += __shfl_xor_sync(0xffffffffu, ss, off);
    }
    __shared__ float sw[8], ssw[8], red[2];
    const int wid = tid >> 5, lane = tid & 31;
    if (lane == 0) { sw[wid] = s; ssw[wid] = ss; }
    __syncthreads();
    if (tid == 0) {
        float S2 = 0.f, SS = 0.f;
        for (int i = 0; i < 8; i++) { S2 += sw[i]; SS += ssw[i]; }
        red[0] = S2; red[1] = SS;
    }
    __syncthreads();
    const float mu  = red[0] * (1.0f / E_DIM);
    const float var = red[1] * (1.0f / E_DIM) - mu * mu;
    const float r   = rsqrtf(var + 1e-5f);
    const float4 g  = *(const float4*)(gamma + tid*4);
    const float4 bt = *(const float4*)(beta  + tid*4);
    float4 o;
    o.x = (e0 - mu) * r * g.x + bt.x;
    o.y = (e1 - mu) * r * g.y + bt.y;
    o.z = (e2 - mu) * r * g.z + bt.z;
    o.w = (e3 - mu) * r * g.w + bt.w;
    *(float4*)(out + base + tid*4) = o;
}

// ---------------------------------------------------------------------------
extern "C" void kernel_launch(void* const* d_in, const int* in_sizes, int n_in,
                              void* d_out, int out_size)
{
    const float* query    = (const float*)d_in[0];
    const float* key      = (const float*)d_in[1];
    const float* value    = (const float*)d_in[2];
    const float* Wq       = (const float*)d_in[3];
    const float* Wk       = (const float*)d_in[4];
    const float* Wv       = (const float*)d_in[5];
    const float* in_proj  = (const float*)d_in[6];
    const float* out_proj = (const float*)d_in[7];
    const float* proj     = (const float*)d_in[8];
    const float* gamma    = (const float*)d_in[9];
    const float* beta     = (const float*)d_in[10];
    float* out = (float*)d_out;

    bf16 *pin, *pqkv, *patt, *pob, *pws, *pwt, *pwa, *pwc;
    float *pf;
    cudaGetSymbolAddress((void**)&pin,  g_in);
    cudaGetSymbolAddress((void**)&pqkv, g_qkv);
    cudaGetSymbolAddress((void**)&patt, g_att);
    cudaGetSymbolAddress((void**)&pob,  g_ob);
    cudaGetSymbolAddress((void**)&pf,   g_f);
    cudaGetSymbolAddress((void**)&pws,  g_ws);
    cudaGetSymbolAddress((void**)&pwt,  g_wt);
    cudaGetSymbolAddress((void**)&pwa,  g_wa);
    cudaGetSymbolAddress((void**)&pwc,  g_wc);

    cudaFuncSetAttribute(gemm_bf<true>,
        cudaFuncAttributeMaxDynamicSharedMemorySize, GEMM_SMEM);
    cudaFuncSetAttribute(gemm_bf<false>,
        cudaFuncAttributeMaxDynamicSharedMemorySize, GEMM_SMEM);
    cudaFuncSetAttribute(attn_mma,
        cudaFuncAttributeMaxDynamicSharedMemorySize, ATTN_SMEM);

    // converts: weights (5M) + inputs (24M); transpose Wq/Wk/Wv
    conv_all<<<29696, 256>>>(in_proj, out_proj, proj, query, key, value,
                             pws, pin);
    transconv<<<dim3(32, 32, 3), dim3(32, 8)>>>(Wq, Wk, Wv, pwt);

    // RoPE-combined A-side weights (17M elems)
    ropew_kernel<<<17408, 256>>>(pws, pwa);

    // weight GEMM: Wc[z] = WA[z] @ WT[z>>3]^T, z = 0..16 (q-scale for z<8)
    gemm_bf<true><<<dim3(8, 8, 17), 256, GEMM_SMEM>>>(
        pwa, pwt, pwc, (int)M1, (int)M1, 1);

    // activation trio: qp/kp/vp = in @ Wc_b^T, [B,S,H,D]
    gemm_bf<true><<<dim3(8, 64, 3), 256, GEMM_SMEM>>>(
        pin, pwc, pqkv, (int)M8, (int)M8, 2);

    // attention -> g_att [B,S,H,D]
    const dim3 ga(S_LEN / 64, B_SZ * H_NUM);   // (16, 128)
    attn_mma<<<ga, 128, ATTN_SMEM>>>(pqkv, pqkv + M8, pqkv + 2 * M8, patt);

    // out_proj -> g_ob [B,S,E]
    gemm_bf<true><<<dim3(8, 64, 1), 256, GEMM_SMEM>>>(
        patt, pws + 3 * M1, pob, 0, 0, 0);

    // final proj -> g_f fp32 [B,S,E] (no gather needed anymore)
    gemm_bf<false><<<dim3(8, 64, 1), 256, GEMM_SMEM>>>(
        pob, pws + 4 * M1, pf, 0, 0, 0);

    // residual + layernorm -> out [B,S,O]
    addln_kernel<<<B_SZ * S_LEN, 256>>>(query, pf, gamma, beta, out);
}

// round 17
// speedup vs baseline: 1.2948x; 1.1061x over previous
#include <cuda_runtime.h>
#include <cuda_bf16.h>
#include <cstdint>

#define S_LEN  1024
#define B_SZ   8
#define E_DIM  1024
#define H_NUM  16
#define D_HEAD 64
#define NBUF   (S_LEN * B_SZ * E_DIM)   /* 8M */
#define M8     (1u << 23)               /* 8M elements */
#define M1     (1u << 20)

typedef __nv_bfloat16 bf16;

// Scratch (no allocations allowed)
__device__ bf16  g_in[3u * M8];     // bf16 inputs [B,S,E]: q | k | v
__device__ bf16  g_qkv[3u * M8];    // qp | kp | vp  [B,S,H,D]
__device__ bf16  g_att[M8];         // attention output
__device__ float g_f[NBUF];         // final proj fp32
__device__ bf16  g_ws[5u * M1];     // Wqa | Wka | Wva | out_proj | proj
__device__ bf16  g_wt[4u * M1];     // WqT | WkT | WvT | out_projT
__device__ bf16  g_wa[18u * M1];    // WA_q(8) | WA_k(8) | Wva copy | proj copy
__device__ bf16  g_wc[18u * M1];    // Wqc(8) | Wkc(8) | Wvc | Wfc

// ===========================================================================
// Family-portable PTX helpers (NO tcgen05 — harness compiles compute_103)
// ===========================================================================
__device__ __forceinline__ uint32_t smem_u32(const void* p) {
    uint32_t a;
    asm("{ .reg .u64 t; cvta.to.shared.u64 t, %1; cvt.u32.u64 %0, t; }"
        : "=r"(a) : "l"(p));
    return a;
}

__device__ __forceinline__ float ex2f(float x) {
    float r;
    asm("ex2.approx.ftz.f32 %0, %1;" : "=f"(r) : "f"(x));
    return r;
}

#define LDSM_X4(d, addr)                                                        \
    asm volatile("ldmatrix.sync.aligned.m8n8.x4.shared.b16 {%0,%1,%2,%3}, [%4];"\
        : "=r"((d)[0]), "=r"((d)[1]), "=r"((d)[2]), "=r"((d)[3]) : "r"(addr))

#define LDSM_X4T(d, addr)                                                       \
    asm volatile("ldmatrix.sync.aligned.m8n8.x4.trans.shared.b16 {%0,%1,%2,%3}, [%4];"\
        : "=r"((d)[0]), "=r"((d)[1]), "=r"((d)[2]), "=r"((d)[3]) : "r"(addr))

#define MMA_BF16(ac, a, b0, b1)                                                 \
    asm volatile("mma.sync.aligned.m16n8k16.row.col.f32.bf16.bf16.f32 "         \
        "{%0,%1,%2,%3}, {%4,%5,%6,%7}, {%8,%9}, {%0,%1,%2,%3};"                 \
        : "+f"((ac)[0]), "+f"((ac)[1]), "+f"((ac)[2]), "+f"((ac)[3])            \
        : "r"((a)[0]), "r"((a)[1]), "r"((a)[2]), "r"((a)[3]),                   \
          "r"(b0), "r"(b1))

#define CP_ASYNC16(s, g)                                                        \
    asm volatile("cp.async.cg.shared.global [%0], [%1], 16;" :: "r"(s), "l"(g))
#define CP_COMMIT() asm volatile("cp.async.commit_group;" ::: "memory")
#define CP_WAIT0()  asm volatile("cp.async.wait_group 0;" ::: "memory")
#define CP_WAIT1()  asm volatile("cp.async.wait_group 1;" ::: "memory")

__device__ __forceinline__ uint32_t packbf(float x, float y) {
    __nv_bfloat162 t = __floats2bfloat162_rn(x, y);
    return *reinterpret_cast<uint32_t*>(&t);
}
__device__ __forceinline__ void unpack2(uint32_t u, float& a, float& b) {
    __nv_bfloat162 t = *reinterpret_cast<__nv_bfloat162*>(&u);
    a = __bfloat162float(t.x); b = __bfloat162float(t.y);
}

#define QSCALE 0.18033688011112043f   /* 0.125 * log2(e) */

// ===========================================================================
// All-bf16 mma.sync GEMM, 3-stage pipeline — R10 shape (CTA 128x128, 2/SM).
// C[m, n] = sum_k A_row(m)[k] * W[n*1024 + k].
// A = A0 + z*zA, row m at m*1024.
// wsel: 0 -> W = W0
//       1 -> W = W0 + ((z>>3)+(z==17))*1M; epilogue scale QSCALE when z<8
//       2 -> W = W0 + (z<2 ? (z*8 + (m_blk>>10))*1M : 16*1M)
// ===========================================================================
#define GTB   (128 * 72 * 2)     /* 18432 B per tile */
#define STAGE (2 * GTB)          /* 36864 B per stage (A + B) */
#define GEMM_SMEM (3 * STAGE)    /* 110592 B */

template<bool OUTBF>
__global__ __launch_bounds__(256, 2) void gemm_bf(
    const bf16* __restrict__ A0, const bf16* __restrict__ W0,
    void* __restrict__ Cv, int zA, int zC, int wsel)
{
    extern __shared__ __align__(16) char smp[];
    const uint32_t s0 = smem_u32(smp);

    const int z = blockIdx.z;
    const int m_blk = blockIdx.y << 7;
    const int n_blk = blockIdx.x << 7;

    const bf16* A = A0 + (size_t)z * (uint32_t)zA;
    const bf16* Bw;
    if (wsel == 1)      Bw = W0 + ((size_t)((z >> 3) + (z == 17 ? 1 : 0)) << 20);
    else if (wsel == 2) Bw = W0 + ((size_t)((z < 2) ? (z * 8 + (m_blk >> 10)) : 16) << 20);
    else                Bw = W0;

    const int tid  = threadIdx.x;
    const int lane = tid & 31;
    const int w    = tid >> 5;
    const int wm   = w >> 1;
    const int wn   = w & 1;

    const bf16* apt[4];
    const bf16* bpt[4];
    uint32_t ast[4], bst[4];
#pragma unroll
    for (int j = 0; j < 4; j++) {
        const int c = tid + 256 * j;
        const int row = c >> 3, sg = (c & 7) << 3;
        apt[j] = A + (size_t)(m_blk + row) * 1024 + sg;
        bpt[j] = Bw + (size_t)(n_blk + row) * 1024 + sg;
        ast[j] = s0 + (uint32_t)(row * 144 + sg * 2);
        bst[j] = s0 + GTB + (uint32_t)(row * 144 + sg * 2);
    }

    const uint32_t a_lm = s0 +
        (uint32_t)((wm * 32 + (lane & 15)) * 144) + ((lane >> 4) << 4);
    const uint32_t b_lm = s0 + GTB +
        (uint32_t)((wn * 64 + (((lane >> 4) & 1) << 3) + (lane & 7)) * 144)
        + (((lane >> 3) & 1) << 4);

    float acc[2][8][4];
#pragma unroll
    for (int mt = 0; mt < 2; mt++)
#pragma unroll
        for (int nt = 0; nt < 8; nt++)
#pragma unroll
            for (int j = 0; j < 4; j++) acc[mt][nt][j] = 0.f;

#pragma unroll
    for (int j = 0; j < 4; j++) {
        CP_ASYNC16(ast[j], apt[j]);
        CP_ASYNC16(bst[j], bpt[j]);
    }
    CP_COMMIT();
#pragma unroll
    for (int j = 0; j < 4; j++) {
        CP_ASYNC16(ast[j] + STAGE, apt[j] + 64);
        CP_ASYNC16(bst[j] + STAGE, bpt[j] + 64);
    }
    CP_COMMIT();
    CP_WAIT1();
    __syncthreads();

    uint32_t cb = 0, lb = 2;
    for (int i = 0; i < 16; i++) {
        if (i < 14) {
            const int ko = (i + 2) << 6;
            const uint32_t lo = lb * STAGE;
#pragma unroll
            for (int j = 0; j < 4; j++) {
                CP_ASYNC16(ast[j] + lo, apt[j] + ko);
                CP_ASYNC16(bst[j] + lo, bpt[j] + ko);
            }
            CP_COMMIT();
        }

        const uint32_t co = cb * STAGE;
        const uint32_t ab = a_lm + co;
        const uint32_t bb = b_lm + co;
#pragma unroll
        for (int ks = 0; ks < 4; ks++) {
            uint32_t af0[4], af1[4];
            LDSM_X4(af0, ab + ks * 32);
            LDSM_X4(af1, ab + ks * 32 + 16 * 144);
            uint32_t bfr[4][4];
#pragma unroll
            for (int bt = 0; bt < 4; bt++)
                LDSM_X4(bfr[bt], bb + ks * 32 + bt * 16 * 144);
#pragma unroll
            for (int nt = 0; nt < 8; nt++) {
                const uint32_t bb0 = (nt & 1) ? bfr[nt >> 1][2] : bfr[nt >> 1][0];
                const uint32_t bb1 = (nt & 1) ? bfr[nt >> 1][3] : bfr[nt >> 1][1];
                MMA_BF16(acc[0][nt], af0, bb0, bb1);
                MMA_BF16(acc[1][nt], af1, bb0, bb1);
            }
        }

        if (i < 14)      CP_WAIT1();
        else if (i == 14) CP_WAIT0();
        __syncthreads();
        cb = (cb == 2) ? 0 : cb + 1;
        lb = (lb == 2) ? 0 : lb + 1;
    }

    // q-side score scale folded into combined weights
    if (wsel == 1 && z < 8) {
#pragma unroll
        for (int mt = 0; mt < 2; mt++)
#pragma unroll
            for (int nt = 0; nt < 8; nt++)
#pragma unroll
                for (int j = 0; j < 4; j++) acc[mt][nt][j] *= QSCALE;
    }

    const int crow = m_blk + wm * 32 + (lane >> 2);
    const int ccol = n_blk + wn * 64 + ((lane & 3) << 1);
    if (OUTBF) {
        bf16* C = (bf16*)Cv + (size_t)z * (uint32_t)zC;
#pragma unroll
        for (int mt = 0; mt < 2; mt++)
#pragma unroll
            for (int nt = 0; nt < 8; nt++) {
                bf16* cp = C + (size_t)(crow + mt * 16) * 1024 + ccol + nt * 8;
                *(uint32_t*)cp = packbf(acc[mt][nt][0], acc[mt][nt][1]);
                *(uint32_t*)(cp + 8 * 1024) = packbf(acc[mt][nt][2], acc[mt][nt][3]);
            }
    } else {
        float* C = (float*)Cv;
#pragma unroll
        for (int mt = 0; mt < 2; mt++)
#pragma unroll
            for (int nt = 0; nt < 8; nt++) {
                float* cp = C + (size_t)(crow + mt * 16) * 1024 + ccol + nt * 8;
                *(float2*)cp = make_float2(acc[mt][nt][0], acc[mt][nt][1]);
                *(float2*)(cp + 8 * 1024) = make_float2(acc[mt][nt][2], acc[mt][nt][3]);
            }
    }
}

// ===========================================================================
// Tensor-core flash attention, [B,S,H,D] layouts, exp2 softmax (scale folded
// into qp). 64 q-rows/CTA, 128 thr, double-buffered 64-row K/V tiles.
// ===========================================================================
#define AT64       (64 * 144)
#define KVST       (2 * AT64)
#define ATTN_SMEM  (AT64 + 2 * KVST)       /* 46080 */

__global__ __launch_bounds__(128) void attn_mma(
    const bf16* __restrict__ qp, const bf16* __restrict__ kp,
    const bf16* __restrict__ vp, bf16* __restrict__ out)
{
    extern __shared__ __align__(16) char asmp[];
    const uint32_t sQ = smem_u32(asmp);
    const uint32_t sK = sQ + AT64;
    const uint32_t sV = sK + AT64;

    const int tid = threadIdx.x, lane = tid & 31, w = tid >> 5;
    const int bh = blockIdx.y, b = bh >> 4, h = bh & 15;
    const int m0 = blockIdx.x << 6;
    const size_t hb = (size_t)b * S_LEN * E_DIM + h * D_HEAD;
    const bf16* qb = qp + hb;
    const bf16* kb = kp + hb;
    const bf16* vb = vp + hb;

#pragma unroll
    for (int j = 0; j < 4; j++) {
        const int c = tid + 128 * j;
        const int rr = c >> 3, sg = (c & 7) << 3;
        CP_ASYNC16(sQ + (uint32_t)(rr * 144 + sg * 2),
                   qb + (size_t)(m0 + rr) * E_DIM + sg);
    }
    CP_COMMIT();

    uint32_t kvso[4];
    size_t kvgo[4];
#pragma unroll
    for (int j = 0; j < 4; j++) {
        const int c = tid + 128 * j;
        const int rr = c >> 3, sg = (c & 7) << 3;
        kvso[j] = (uint32_t)(rr * 144 + sg * 2);
        kvgo[j] = (size_t)rr * E_DIM + sg;
    }

    const uint32_t aQ = sQ + (uint32_t)((w * 16 + (lane & 15)) * 144) + ((lane >> 4) << 4);
    const uint32_t bKr = (uint32_t)(((((lane >> 4) & 1) << 3) + (lane & 7)) * 144)
                       + (((lane >> 3) & 1) << 4);
    const uint32_t bVr = (uint32_t)(((lane & 7) + (((lane >> 3) & 1) << 3)) * 144)
                       + ((lane >> 4) << 4);

    float m0r = -1e30f, m1r = -1e30f, l0 = 0.f, l1 = 0.f;
    float o[8][4];
#pragma unroll
    for (int nt = 0; nt < 8; nt++)
#pragma unroll
        for (int j = 0; j < 4; j++) o[nt][j] = 0.f;

#pragma unroll
    for (int j = 0; j < 4; j++) {
        CP_ASYNC16(sK + kvso[j], kb + kvgo[j]);
        CP_ASYNC16(sV + kvso[j], vb + kvgo[j]);
    }
    CP_COMMIT();

    for (int t = 0; t < 16; t++) {
        if (t < 15) {
            const uint32_t po = (uint32_t)((t + 1) & 1) * KVST;
            const size_t go = (size_t)(t + 1) * 64 * E_DIM;
#pragma unroll
            for (int j = 0; j < 4; j++) {
                CP_ASYNC16(sK + po + kvso[j], kb + go + kvgo[j]);
                CP_ASYNC16(sV + po + kvso[j], vb + go + kvgo[j]);
            }
            CP_COMMIT();
            CP_WAIT1();
        } else {
            CP_WAIT0();
        }
        __syncthreads();

        const uint32_t po = (uint32_t)(t & 1) * KVST;
        const uint32_t bK = sK + po + bKr;
        const uint32_t bV = sV + po + bVr;

        float s[8][4];
#pragma unroll
        for (int nt = 0; nt < 8; nt++)
#pragma unroll
            for (int j = 0; j < 4; j++) s[nt][j] = 0.f;

#pragma unroll
        for (int ks = 0; ks < 4; ks++) {
            uint32_t aq[4];
            LDSM_X4(aq, aQ + ks * 32);
#pragma unroll
            for (int bt = 0; bt < 4; bt++) {
                uint32_t bk[4];
                LDSM_X4(bk, bK + bt * (16 * 144) + ks * 32);
                MMA_BF16(s[2 * bt], aq, bk[0], bk[1]);
                MMA_BF16(s[2 * bt + 1], aq, bk[2], bk[3]);
            }
        }

        // online softmax in log2 domain (scale pre-folded into qp)
        float mx0 = m0r, mx1 = m1r;
#pragma unroll
        for (int nt = 0; nt < 8; nt++) {
            mx0 = fmaxf(mx0, fmaxf(s[nt][0], s[nt][1]));
            mx1 = fmaxf(mx1, fmaxf(s[nt][2], s[nt][3]));
        }
        mx0 = fmaxf(mx0, __shfl_xor_sync(0xffffffffu, mx0, 1, 4));
        mx0 = fmaxf(mx0, __shfl_xor_sync(0xffffffffu, mx0, 2, 4));
        mx1 = fmaxf(mx1, __shfl_xor_sync(0xffffffffu, mx1, 1, 4));
        mx1 = fmaxf(mx1, __shfl_xor_sync(0xffffffffu, mx1, 2, 4));
        const float f0 = ex2f(m0r - mx0), f1 = ex2f(m1r - mx1);
        float r0 = 0.f, r1 = 0.f;
#pragma unroll
        for (int nt = 0; nt < 8; nt++) {
            s[nt][0] = ex2f(s[nt][0] - mx0);
            s[nt][1] = ex2f(s[nt][1] - mx0);
            s[nt][2] = ex2f(s[nt][2] - mx1);
            s[nt][3] = ex2f(s[nt][3] - mx1);
            r0 += s[nt][0] + s[nt][1];
            r1 += s[nt][2] + s[nt][3];
        }
        r0 += __shfl_xor_sync(0xffffffffu, r0, 1, 4);
        r0 += __shfl_xor_sync(0xffffffffu, r0, 2, 4);
        r1 += __shfl_xor_sync(0xffffffffu, r1, 1, 4);
        r1 += __shfl_xor_sync(0xffffffffu, r1, 2, 4);
        l0 = l0 * f0 + r0; l1 = l1 * f1 + r1;
        m0r = mx0; m1r = mx1;
#pragma unroll
        for (int nt = 0; nt < 8; nt++) {
            o[nt][0] *= f0; o[nt][1] *= f0;
            o[nt][2] *= f1; o[nt][3] *= f1;
        }

#pragma unroll
        for (int kk = 0; kk < 4; kk++) {
            uint32_t pa[4];
            pa[0] = packbf(s[2 * kk][0], s[2 * kk][1]);
            pa[1] = packbf(s[2 * kk][2], s[2 * kk][3]);
            pa[2] = packbf(s[2 * kk + 1][0], s[2 * kk + 1][1]);
            pa[3] = packbf(s[2 * kk + 1][2], s[2 * kk + 1][3]);
            const uint32_t vbase = bV + kk * (16 * 144);
#pragma unroll
            for (int vt = 0; vt < 4; vt++) {
                uint32_t bv[4];
                LDSM_X4T(bv, vbase + vt * 32);
                MMA_BF16(o[2 * vt], pa, bv[0], bv[1]);
                MMA_BF16(o[2 * vt + 1], pa, bv[2], bv[3]);
            }
        }
        __syncthreads();
    }

    const int row0 = m0 + w * 16 + (lane >> 2);
    const int col = (lane & 3) << 1;
    const float i0 = 1.f / l0, i1 = 1.f / l1;
    bf16* ob0 = out + hb + (size_t)row0 * E_DIM;
    bf16* ob1 = ob0 + 8 * E_DIM;
#pragma unroll
    for (int nt = 0; nt < 8; nt++) {
        *(uint32_t*)(ob0 + nt * 8 + col) = packbf(o[nt][0] * i0, o[nt][1] * i0);
        *(uint32_t*)(ob1 + nt * 8 + col) = packbf(o[nt][2] * i1, o[nt][3] * i1);
    }
}

// ===========================================================================
// conv_all: in_proj(3M)+out_proj(1M)+proj(1M) -> g_ws; inputs(24M) -> g_in
// ===========================================================================
__global__ __launch_bounds__(256) void conv_all(
    const float* __restrict__ inp, const float* __restrict__ outp,
    const float* __restrict__ projw,
    const float* __restrict__ q, const float* __restrict__ k,
    const float* __restrict__ v,
    bf16* __restrict__ wdst, bf16* __restrict__ idst)
{
    const int idx = blockIdx.x * 256 + threadIdx.x;
    const float* src;
    bf16* dst;
    if (idx < (5 << 18)) {                    // weights: 1.25M threads / 5M elems
        const size_t e = (size_t)idx << 2;
        const int seg = (int)(e >> 20);
        const size_t off = e & 0xFFFFFu;
        if (seg < 3)      src = inp + ((size_t)seg << 20) + off;
        else if (seg == 3) src = outp + off;
        else               src = projw + off;
        dst = wdst + e;
    } else {                                  // inputs: 6M threads / 24M elems
        const size_t e = (size_t)(idx - (5 << 18)) << 2;
        const int seg = (int)(e >> 23);
        const size_t off = e & (M8 - 1);
        src = ((seg == 0) ? q : (seg == 1) ? k : v) + off;
        dst = idst + e;
    }
    const float4 t = *(const float4*)src;
    uint2 pv;
    pv.x = packbf(t.x, t.y);
    pv.y = packbf(t.z, t.w);
    *reinterpret_cast<uint2*>(dst) = pv;
}

// ===========================================================================
// Tiled transpose-convert: Wq/Wk/Wv fp32 + out_proj(bf16 NOT needed: fp32 src)
// -> bf16 transposed g_wt. dst[a*1024+b] = src[b*1024+a].
// grid (32, 32, 4), block (32, 8). z==3 uses out_proj fp32 input.
// ===========================================================================
__global__ __launch_bounds__(256) void transconv(
    const float* __restrict__ Wq, const float* __restrict__ Wk,
    const float* __restrict__ Wv, const float* __restrict__ outp,
    bf16* __restrict__ wt)
{
    __shared__ float tile[32][33];
    const int z = blockIdx.z;
    const float* src = (z == 0) ? Wq : (z == 1) ? Wk : (z == 2) ? Wv : outp;
    bf16* dst = wt + ((size_t)z << 20);
    const int x0 = blockIdx.x << 5, e0 = blockIdx.y << 5;
    const int tx = threadIdx.x, ty = threadIdx.y;
#pragma unroll
    for (int i = ty; i < 32; i += 8)
        tile[i][tx] = src[(size_t)(e0 + i) * 1024 + x0 + tx];
    __syncthreads();
#pragma unroll
    for (int i = ty; i < 32; i += 8)
        dst[(size_t)(x0 + i) * 1024 + e0 + tx] = __float2bfloat16(tile[tx][i]);
}

// ===========================================================================
// ropew: build WA = [Wqa*R_b (b=0..7) | Wka*R_b (b=0..7) | Wva | proj]  (18M)
// ===========================================================================
__global__ __launch_bounds__(256) void ropew_kernel(
    const bf16* __restrict__ ws, bf16* __restrict__ wa)
{
    const int idx = blockIdx.x * 256 + threadIdx.x;   // 18M/4 threads
    const size_t gi = (size_t)idx << 2;
    const int z = (int)(gi >> 20);
    const uint32_t r = (uint32_t)(gi & 0xFFFFFu);
    if (z >= 16) {
        const size_t so = (z == 16) ? (2u << 20) : (4u << 20);
        *(uint2*)(wa + gi) = *(const uint2*)(ws + so + r);
        return;
    }
    const bf16* W = ws + ((z >= 8) ? (1u << 20) : 0u);
    const float bpos = (float)(z & 7);
    const uint32_t n = r >> 10, e = r & 1023u;
    const int jj = (int)(e & 63);
    const bool lo = (jj < 32);
    const size_t base = (size_t)n * 1024 + e;
    uint2 tp = *(const uint2*)(W + base);
    uint2 tq = *(const uint2*)(W + base + (lo ? 32 : -32));
    float p[4], q4[4];
    unpack2(tp.x, p[0], p[1]); unpack2(tp.y, p[2], p[3]);
    unpack2(tq.x, q4[0], q4[1]); unpack2(tq.y, q4[2], q4[3]);
    float v[4];
#pragma unroll
    for (int c = 0; c < 4; c++) {
        const int j2 = lo ? (jj + c) : (jj + c - 32);
        const float inv = __expf(-0.28782313662425575f * (float)j2);
        float sn, cs;
        __sincosf(bpos * inv, &sn, &cs);
        v[c] = lo ? (p[c] * cs + q4[c] * sn) : (p[c] * cs - q4[c] * sn);
    }
    uint2 pv;
    pv.x = packbf(v[0], v[1]);
    pv.y = packbf(v[2], v[3]);
    *(uint2*)(wa + gi) = pv;
}

// ---------------------------------------------------------------------------
// x = query + ob ; LayerNorm(last dim) * gamma + beta.
// ---------------------------------------------------------------------------
__global__ __launch_bounds__(256) void addln_kernel(
    const float* __restrict__ qin, const float* __restrict__ ob,
    const float* __restrict__ gamma, const float* __restrict__ beta,
    float* __restrict__ out)
{
    const int row = blockIdx.x;
    const int tid = threadIdx.x;
    const size_t base = (size_t)row * E_DIM;

    const float4 a = *(const float4*)(qin + base + tid*4);
    const float4 c = *(const float4*)(ob  + base + tid*4);
    const float e0 = a.x + c.x, e1 = a.y + c.y, e2 = a.z + c.z, e3 = a.w + c.w;
    float s  = e0 + e1 + e2 + e3;
    float ss = e0*e0 + e1*e1 + e2*e2 + e3*e3;
#pragma unroll
    for (int off = 16; off > 0; off >>= 1) {
        s  += __shfl_xor_sync(0xffffffffu, s,  off);
        ss += __shfl_xor_sync(0xffffffffu, ss, off);
    }
    __shared__ float sw[8], ssw[8], red[2];
    const int wid = tid >> 5, lane = tid & 31;
    if (lane == 0) { sw[wid] = s; ssw[wid] = ss; }
    __syncthreads();
    if (tid == 0) {
        float S2 = 0.f, SS = 0.f;
        for (int i = 0; i < 8; i++) { S2 += sw[i]; SS += ssw[i]; }
        red[0] = S2; red[1] = SS;
    }
    __syncthreads();
    const float mu  = red[0] * (1.0f / E_DIM);
    const float var = red[1] * (1.0f / E_DIM) - mu * mu;
    const float r   = rsqrtf(var + 1e-5f);
    const float4 g  = *(const float4*)(gamma + tid*4);
    const float4 bt = *(const float4*)(beta  + tid*4);
    float4 o;
    o.x = (e0 - mu) * r * g.x + bt.x;
    o.y = (e1 - mu) * r * g.y + bt.y;
    o.z = (e2 - mu) * r * g.z + bt.z;
    o.w = (e3 - mu) * r * g.w + bt.w;
    *(float4*)(out + base + tid*4) = o;
}

// ---------------------------------------------------------------------------
extern "C" void kernel_launch(void* const* d_in, const int* in_sizes, int n_in,
                              void* d_out, int out_size)
{
    const float* query    = (const float*)d_in[0];
    const float* key      = (const float*)d_in[1];
    const float* value    = (const float*)d_in[2];
    const float* Wq       = (const float*)d_in[3];
    const float* Wk       = (const float*)d_in[4];
    const float* Wv       = (const float*)d_in[5];
    const float* in_proj  = (const float*)d_in[6];
    const float* out_proj = (const float*)d_in[7];
    const float* proj     = (const float*)d_in[8];
    const float* gamma    = (const float*)d_in[9];
    const float* beta     = (const float*)d_in[10];
    float* out = (float*)d_out;

    bf16 *pin, *pqkv, *patt, *pws, *pwt, *pwa, *pwc;
    float *pf;
    cudaGetSymbolAddress((void**)&pin,  g_in);
    cudaGetSymbolAddress((void**)&pqkv, g_qkv);
    cudaGetSymbolAddress((void**)&patt, g_att);
    cudaGetSymbolAddress((void**)&pf,   g_f);
    cudaGetSymbolAddress((void**)&pws,  g_ws);
    cudaGetSymbolAddress((void**)&pwt,  g_wt);
    cudaGetSymbolAddress((void**)&pwa,  g_wa);
    cudaGetSymbolAddress((void**)&pwc,  g_wc);

    cudaFuncSetAttribute(gemm_bf<true>,
        cudaFuncAttributeMaxDynamicSharedMemorySize, GEMM_SMEM);
    cudaFuncSetAttribute(gemm_bf<false>,
        cudaFuncAttributeMaxDynamicSharedMemorySize, GEMM_SMEM);
    cudaFuncSetAttribute(attn_mma,
        cudaFuncAttributeMaxDynamicSharedMemorySize, ATTN_SMEM);

    // converts: weights (5M) + inputs (24M); transposes (Wq,Wk,Wv,out_proj)
    conv_all<<<29696, 256>>>(in_proj, out_proj, proj, query, key, value,
                             pws, pin);
    transconv<<<dim3(32, 32, 4), dim3(32, 8)>>>(Wq, Wk, Wv, out_proj, pwt);

    // RoPE-combined A-side weights + copies (18M elems)
    ropew_kernel<<<18432, 256>>>(pws, pwa);

    // weight GEMM batch, z = 0..17:
    //   z<8:  Wqc_b = (Wqa R_b) @ WqT^T * QSCALE
    //   8-15: Wkc_b = (Wka R_b) @ WkT^T
    //   16:   Wvc   = Wva @ WvT^T
    //   17:   Wfc   = proj @ out_projT^T  (= proj . out_proj)
    gemm_bf<true><<<dim3(8, 8, 18), 256, GEMM_SMEM>>>(
        pwa, pwt, pwc, (int)M1, (int)M1, 1);

    // activation trio: qp/kp/vp = in @ Wc_b^T, [B,S,H,D]
    gemm_bf<true><<<dim3(8, 64, 3), 256, GEMM_SMEM>>>(
        pin, pwc, pqkv, (int)M8, (int)M8, 2);

    // attention -> g_att [B,S,H,D]
    const dim3 ga(S_LEN / 64, B_SZ * H_NUM);   // (16, 128)
    attn_mma<<<ga, 128, ATTN_SMEM>>>(pqkv, pqkv + M8, pqkv + 2 * M8, patt);

    // fused out_proj+proj: f = att @ Wfc^T -> fp32 [B,S,E]
    gemm_bf<false><<<dim3(8, 64, 1), 256, GEMM_SMEM>>>(
        patt, pwc + 17 * M1, pf, 0, 0, 0);

    // residual + layernorm -> out [B,S,O]
    addln_kernel<<<B_SZ * S_LEN, 256>>>(query, pf, gamma, beta, out);
}